// round 14
// baseline (speedup 1.0000x reference)
#include <cuda_runtime.h>
#include <math_constants.h>
#include <math.h>
#include <cstdint>

#define BATCH 8
#define NPTS 16384
#define NSUB 2048
#define DZ 256
#define DH 256
#define FPSC 8
#define PPC (NPTS/FPSC)
#define PPT (PPC/1024)

#define LOG2E_F 1.4426950408889634f
#define LN2_F   0.6931471805599453f

typedef unsigned long long u64;

__device__ __forceinline__ float ex2(float x) {
    float y;
    asm("ex2.approx.ftz.f32 %0, %1;" : "=f"(y) : "f"(x));
    return y;
}
__device__ __forceinline__ u64 pack2(float lo, float hi) {
    u64 r;
    asm("mov.b64 %0, {%1, %2};" : "=l"(r) : "f"(lo), "f"(hi));
    return r;
}
__device__ __forceinline__ u64 dup2(float v) {
    u64 r;
    asm("mov.b64 %0, {%1, %1};" : "=l"(r) : "f"(v));
    return r;
}
__device__ __forceinline__ u64 fma2(u64 a, u64 b, u64 c) {
    u64 d;
    asm("fma.rn.f32x2 %0, %1, %2, %3;" : "=l"(d) : "l"(a), "l"(b), "l"(c));
    return d;
}
__device__ __forceinline__ void unpack2(u64 r, float& lo, float& hi) {
    asm("mov.b64 {%0, %1}, %2;" : "=f"(lo), "=f"(hi) : "l"(r));
}

// ---- scratch (device globals; allocation is forbidden) ----
__device__ float g_tsub[BATCH*NSUB*3];
__device__ float g_tsub_sq[BATCH*NSUB];
__device__ float g_tmpl_sq[NSUB];
__device__ float g_lu[BATCH*NSUB];
__device__ float g_lv[BATCH*NSUB];
__device__ float g_perm[BATCH*NSUB*3];
__device__ float g_z[BATCH*DZ];
__device__ float g_bb[BATCH*DH];
__device__ float g_x1[BATCH*NSUB*3];
__device__ float g_x1_sq[BATCH*NSUB];
__device__ float g_f1[BATCH*NSUB];
__device__ float g_g1[BATCH*NSUB];
__device__ float g_f2[BATCH*NSUB];
__device__ float g_g2[BATCH*NSUB];
__device__ float g_f3[BATCH*NSUB];
__device__ float g_g3[BATCH*NSUB];
__device__ double g_vel_sum;
__device__ double g_ot_sum;
__device__ double g_reg_sum;

__global__ void k_init() { g_vel_sum = 0.0; g_ot_sum = 0.0; g_reg_sum = 0.0; }

__global__ void k_zero_all() {
    int i = blockIdx.x * blockDim.x + threadIdx.x;
    if (i < BATCH*NSUB) {
        g_lu[i] = 0.f; g_lv[i] = 0.f;
        g_f1[i] = 0.f; g_g1[i] = 0.f;
        g_f2[i] = 0.f; g_g2[i] = 0.f;
        g_f3[i] = 0.f; g_g3[i] = 0.f;
    }
}

__global__ void k_tmpl(const float* __restrict__ tmpl) {
    __shared__ double sred[256];
    int n = blockIdx.x * 256 + threadIdx.x;
    float tx = tmpl[n*3+0], ty = tmpl[n*3+1], tz = tmpl[n*3+2];
    float sq = tx*tx + ty*ty + tz*tz;
    g_tmpl_sq[n] = sq;
    float d = sqrtf(sq) - 1.0f;
    sred[threadIdx.x] = (double)(d * d);
    __syncthreads();
    for (int s = 128; s; s >>= 1) {
        if (threadIdx.x < s) sred[threadIdx.x] += sred[threadIdx.x + s];
        __syncthreads();
    }
    if (threadIdx.x == 0) atomicAdd(&g_reg_sum, sred[0]);
}

// ---------------- FPS over an 8-CTA cluster per batch (known good, R13) ----------------
__device__ __forceinline__ void st_cluster_f4(unsigned int saddr, unsigned int rank, float4 v) {
    unsigned int ra;
    asm volatile("mapa.shared::cluster.u32 %0, %1, %2;" : "=r"(ra) : "r"(saddr), "r"(rank));
    asm volatile("st.shared::cluster.v4.f32 [%0], {%1,%2,%3,%4};"
                 :: "r"(ra), "f"(v.x), "f"(v.y), "f"(v.z), "f"(v.w) : "memory");
}
__device__ __forceinline__ void st_cluster_i32(unsigned int saddr, unsigned int rank, int v) {
    unsigned int ra;
    asm volatile("mapa.shared::cluster.u32 %0, %1, %2;" : "=r"(ra) : "r"(saddr), "r"(rank));
    asm volatile("st.shared::cluster.b32 [%0], %1;" :: "r"(ra), "r"(v) : "memory");
}
#define CLUSTER_SYNC_() do { \
    asm volatile("barrier.cluster.arrive.aligned;" ::: "memory"); \
    asm volatile("barrier.cluster.wait.aligned;" ::: "memory"); } while (0)

__global__ void __launch_bounds__(1024) __cluster_dims__(FPSC, 1, 1)
k_fps(const float* __restrict__ target) {
    __shared__ float ys[PPC], zs[PPC];
    __shared__ float rv[32]; __shared__ int ri[32];
    __shared__ float4 s_mb[2][FPSC]; __shared__ int s_mbi[2][FPSC];
    __shared__ float4 s_cand; __shared__ float s_bv; __shared__ int s_bi;
    int tid = threadIdx.x;
    unsigned int rank;
    asm("mov.u32 %0, %%cluster_ctarank;" : "=r"(rank));
    int b = blockIdx.x / FPSC;
    int base = (int)rank * PPC;
    const float* tg = target + (size_t)b * NPTS * 3 + (size_t)base * 3;
    float rx[PPT], dist[PPT];
#pragma unroll
    for (int j = 0; j < PPT; j++) {
        int n = tid + j * 1024;
        rx[j] = tg[n*3+0];
        ys[n] = tg[n*3+1];
        zs[n] = tg[n*3+2];
        dist[j] = CUDART_INF_F;
    }
    __syncthreads();
    if (tid == 0) {
        float4 c = (rank == 0) ? make_float4(rx[0], ys[0], zs[0], 1.0f)
                               : make_float4(0.f, 0.f, 0.f, -1.0f);
        unsigned int a4 = (unsigned int)__cvta_generic_to_shared(&s_mb[0][rank]);
        unsigned int ai = (unsigned int)__cvta_generic_to_shared(&s_mbi[0][rank]);
        for (unsigned int r = 0; r < FPSC; r++) {
            st_cluster_f4(a4, r, c);
            st_cluster_i32(ai, r, (rank == 0) ? 0 : base);
        }
    }
    CLUSTER_SYNC_();
    int par = 0;
    for (int i = 0; i < NSUB; i++) {
        float bvw = -CUDART_INF_F; int biw = 0x7fffffff;
        float cx = 0.f, cy = 0.f, cz = 0.f;
#pragma unroll
        for (int r = 0; r < FPSC; r++) {
            float4 c = s_mb[par][r]; int ci = s_mbi[par][r];
            if (c.w > bvw || (c.w == bvw && ci < biw)) {
                bvw = c.w; biw = ci; cx = c.x; cy = c.y; cz = c.z;
            }
        }
        if (rank == 0 && tid == 0) {
            float* o = &g_tsub[(b*NSUB + i)*3];
            o[0] = cx; o[1] = cy; o[2] = cz;
            g_tsub_sq[b*NSUB + i] = cx*cx + cy*cy + cz*cz;
        }
        float bv = -1.0f; int bi = base;
#pragma unroll
        for (int j = 0; j < PPT; j++) {
            int n = tid + j * 1024;
            float dx = __fadd_rn(rx[j], -cx);
            float dy = __fadd_rn(ys[n], -cy);
            float dz = __fadd_rn(zs[n], -cz);
            float d  = __fadd_rn(__fadd_rn(__fmul_rn(dx,dx), __fmul_rn(dy,dy)), __fmul_rn(dz,dz));
            float nd = fminf(dist[j], d);
            dist[j] = nd;
            if (nd > bv) { bv = nd; bi = base + n; }
        }
#pragma unroll
        for (int off = 16; off; off >>= 1) {
            float ov = __shfl_xor_sync(0xffffffffu, bv, off);
            int   oi = __shfl_xor_sync(0xffffffffu, bi, off);
            if (ov > bv || (ov == bv && oi < bi)) { bv = ov; bi = oi; }
        }
        if ((tid & 31) == 0) { rv[tid >> 5] = bv; ri[tid >> 5] = bi; }
        __syncthreads();
        if (tid < 32) {
            bv = rv[tid]; bi = ri[tid];
#pragma unroll
            for (int off = 16; off; off >>= 1) {
                float ov = __shfl_xor_sync(0xffffffffu, bv, off);
                int   oi = __shfl_xor_sync(0xffffffffu, bi, off);
                if (ov > bv || (ov == bv && oi < bi)) { bv = ov; bi = oi; }
            }
            if (tid == 0) { s_bv = bv; s_bi = bi; }
        }
        __syncthreads();
        int wbi = s_bi;
        int loc = wbi - base;
        if ((loc & 1023) == tid) {
            int j = loc >> 10;
            float x = (j == 0) ? rx[0] : rx[PPT-1];
            s_cand = make_float4(x, ys[loc], zs[loc], s_bv);
        }
        __syncthreads();
        if (tid < FPSC) {
            unsigned int a4 = (unsigned int)__cvta_generic_to_shared(&s_mb[par^1][rank]);
            unsigned int ai = (unsigned int)__cvta_generic_to_shared(&s_mbi[par^1][rank]);
            st_cluster_f4(a4, (unsigned int)tid, s_cand);
            st_cluster_i32(ai, (unsigned int)tid, wbi);
        }
        CLUSTER_SYNC_();
        par ^= 1;
    }
}

struct RunDesc {
    const float *aPts, *aSq, *bPts, *bSq, *w;
    float *out;
    int aPB, aSB, bPB, bSB;
    float wMul, wAdd, coeff, outScale;  // log2-domain
};

// out[b][r] = outScale * ln-LSE_m(...), log2-domain args.
// 8 rows per lane-group, dot products via packed fma.rn.f32x2 (bit-identical to scalar).
// Online per-row max with FSEL recurrence (unchanged semantics).
__global__ void __launch_bounds__(128, 7) k_lse2(RunDesc d0, RunDesc d1) {
    __shared__ float4 sB[NSUB];
    RunDesc d = (blockIdx.z == 0) ? d0 : d1;
    int b = blockIdx.y, tid = threadIdx.x;
    float coeff = d.coeff;
    float s = -2.0f * coeff;
    for (int m = tid; m < NSUB; m += 128) {
        const float* bp = d.bPts + b*d.bPB + m*3;
        float wv = fmaf(d.w[b*NSUB + m], d.wMul, d.wAdd);
        wv = fmaf(d.bSq[b*d.bSB + m], coeff, wv);
        sB[m] = make_float4(s*bp[0], s*bp[1], s*bp[2], wv);
    }
    __syncthreads();
    int warp = tid >> 5, lane = tid & 31;
    int r0 = blockIdx.x * 32 + warp * 8;
    u64 axp[4], ayp[4], azp[4];
    float A[8], mr[8], sr[8];
#pragma unroll
    for (int p = 0; p < 4; p++) {
        const float* a0 = d.aPts + b*d.aPB + (r0 + 2*p)*3;
        const float* a1 = d.aPts + b*d.aPB + (r0 + 2*p + 1)*3;
        axp[p] = pack2(a0[0], a1[0]);
        ayp[p] = pack2(a0[1], a1[1]);
        azp[p] = pack2(a0[2], a1[2]);
    }
#pragma unroll
    for (int q = 0; q < 8; q++) {
        A[q] = coeff * d.aSq[b*d.aSB + r0 + q];
        mr[q] = -CUDART_INF_F; sr[q] = 0.f;
    }
    for (int m = lane; m < NSUB; m += 32) {
        float4 pb = sB[m];
        u64 bx2 = dup2(pb.x), by2 = dup2(pb.y), bz2 = dup2(pb.z), bw2 = dup2(pb.w);
#pragma unroll
        for (int p = 0; p < 4; p++) {
            u64 acc = fma2(axp[p], bx2, fma2(ayp[p], by2, fma2(azp[p], bz2, bw2)));
            float a0, a1;
            unpack2(acc, a0, a1);
            {
                int q = 2*p;
                float diff = a0 - mr[q];
                float nm = fmaxf(mr[q], a0);
                float e  = ex2(-fabsf(diff));
                bool  gt = diff > 0.0f;
                sr[q] = fmaf(sr[q], gt ? e : 1.0f, gt ? 1.0f : e);
                mr[q] = nm;
            }
            {
                int q = 2*p + 1;
                float diff = a1 - mr[q];
                float nm = fmaxf(mr[q], a1);
                float e  = ex2(-fabsf(diff));
                bool  gt = diff > 0.0f;
                sr[q] = fmaf(sr[q], gt ? e : 1.0f, gt ? 1.0f : e);
                mr[q] = nm;
            }
        }
    }
#pragma unroll
    for (int q = 0; q < 8; q++) {
#pragma unroll
        for (int off = 16; off; off >>= 1) {
            float om = __shfl_xor_sync(0xffffffffu, mr[q], off);
            float os = __shfl_xor_sync(0xffffffffu, sr[q], off);
            float nm = fmaxf(mr[q], om);
            sr[q] = fmaf(sr[q], ex2(mr[q]-nm), os * ex2(om-nm));
            mr[q] = nm;
        }
    }
    if (lane == 0) {
#pragma unroll
        for (int q = 0; q < 8; q++) {
            float lse = fmaf(mr[q] + A[q], LN2_F, logf(sr[q]));
            d.out[b*NSUB + r0 + q] = d.outScale * lse;
        }
    }
}

// target_perm = P @ target_sub; log2-domain args. (known good, R13)
__global__ void __launch_bounds__(256) k_perm(const float* __restrict__ tmpl) {
    __shared__ float4 sB[NSUB];
    int b = blockIdx.y, tid = threadIdx.x;
    const float coeff = -20.0f * LOG2E_F;
    const float s = 40.0f * LOG2E_F;
    const float inv_s = 1.0f / (40.0f * LOG2E_F);
    for (int m = tid; m < NSUB; m += 256) {
        const float* bp = &g_tsub[(b*NSUB + m)*3];
        float wv = fmaf(g_tsub_sq[b*NSUB + m], coeff, g_lv[b*NSUB + m] * LOG2E_F);
        sB[m] = make_float4(s*bp[0], s*bp[1], s*bp[2], wv);
    }
    __syncthreads();
    int warp = tid >> 5, lane = tid & 31;
    int r0 = blockIdx.x * 32 + warp * 4;
    float ax[4], ay[4], az[4], C[4], px[4], py[4], pz[4];
#pragma unroll
    for (int q = 0; q < 4; q++) {
        const float* ap = &tmpl[(r0 + q)*3];
        ax[q] = ap[0]; ay[q] = ap[1]; az[q] = ap[2];
        C[q] = fmaf(g_tmpl_sq[r0 + q], coeff, g_lu[b*NSUB + r0 + q] * LOG2E_F);
        px[q] = 0.f; py[q] = 0.f; pz[q] = 0.f;
    }
    for (int m = lane; m < NSUB; m += 32) {
        float4 pb = sB[m];
#pragma unroll
        for (int q = 0; q < 4; q++) {
            float arg = fmaf(ax[q], pb.x, fmaf(ay[q], pb.y, fmaf(az[q], pb.z, pb.w)));
            float e = ex2(arg + C[q]);
            px[q] = fmaf(e, pb.x, px[q]);
            py[q] = fmaf(e, pb.y, py[q]);
            pz[q] = fmaf(e, pb.z, pz[q]);
        }
    }
#pragma unroll
    for (int q = 0; q < 4; q++) {
#pragma unroll
        for (int off = 16; off; off >>= 1) {
            px[q] += __shfl_xor_sync(0xffffffffu, px[q], off);
            py[q] += __shfl_xor_sync(0xffffffffu, py[q], off);
            pz[q] += __shfl_xor_sync(0xffffffffu, pz[q], off);
        }
    }
    if (lane == 0) {
#pragma unroll
        for (int q = 0; q < 4; q++) {
            float* o = &g_perm[(b*NSUB + r0 + q)*3];
            o[0] = px[q] * inv_s; o[1] = py[q] * inv_s; o[2] = pz[q] * inv_s;
        }
    }
}

__global__ void __launch_bounds__(256) k_enc(const float* __restrict__ W, const float* __restrict__ be) {
    __shared__ float sP[NSUB*3];
    int b = blockIdx.x, tid = threadIdx.x;
    for (int i = tid; i < NSUB*3; i += 256) sP[i] = g_tsub[b*NSUB*3 + i];
    __syncthreads();
    float wx = W[tid], wy = W[256 + tid], wz = W[512 + tid], bb = be[tid];
    float zm = 0.0f;
    for (int m = 0; m < NSUB; m++) {
        float v = fmaf(sP[m*3], wx, fmaf(sP[m*3+1], wy, fmaf(sP[m*3+2], wz, bb)));
        zm = fmaxf(zm, fmaxf(v, 0.0f));
    }
    g_z[b*DZ + tid] = zm;
}

__global__ void __launch_bounds__(256) k_bias(const float* __restrict__ W1, const float* __restrict__ b1,
                                              const float* __restrict__ t) {
    __shared__ float sZ[DZ];
    int b = blockIdx.x, c = threadIdx.x;
    sZ[c] = g_z[b*DZ + c];
    __syncthreads();
    float tc = fminf(fmaxf(t[b], 1e-5f), 1.0f - 1e-5f);
    float acc = fmaf(tc, W1[3*DH + c], b1[c]);
    for (int k = 0; k < DZ; k++)
        acc = fmaf(sZ[k], W1[(4 + k)*DH + c], acc);
    g_bb[b*DH + c] = acc;
}

__global__ void __launch_bounds__(256) k_mlp(const float* __restrict__ tmpl, const float* __restrict__ W1,
                                             const float* __restrict__ W2, const float* __restrict__ b2,
                                             const float* __restrict__ t) {
    __shared__ float sBB[DH], sWa[DH], sWb[DH], sWc[DH], sW2[DH*3];
    int b = blockIdx.y, tid = threadIdx.x;
    sBB[tid] = g_bb[b*DH + tid];
    sWa[tid] = W1[0*DH + tid];
    sWb[tid] = W1[1*DH + tid];
    sWc[tid] = W1[2*DH + tid];
    for (int i = tid; i < DH*3; i += 256) sW2[i] = W2[i];
    __syncthreads();
    int warp = tid >> 5, lane = tid & 31;
    float tc = fminf(fmaxf(t[b], 1e-5f), 1.0f - 1e-5f);
    float u = 1.0f - tc;
    float b20 = b2[0], b21 = b2[1], b22 = b2[2];
    double vacc = 0.0;
    for (int q = 0; q < 4; q++) {
        int p = blockIdx.x * 32 + warp * 4 + q;
        float tmx = tmpl[p*3], tmy = tmpl[p*3+1], tmz = tmpl[p*3+2];
        const float* pp = &g_perm[(b*NSUB + p)*3];
        float pmx = pp[0], pmy = pp[1], pmz = pp[2];
        float x0 = u*tmx + tc*pmx, x1 = u*tmy + tc*pmy, x2 = u*tmz + tc*pmz;
        float a0 = 0.f, a1 = 0.f, a2 = 0.f;
#pragma unroll
        for (int k = 0; k < 8; k++) {
            int c = lane + k*32;
            float h = fmaf(x0, sWa[c], fmaf(x1, sWb[c], fmaf(x2, sWc[c], sBB[c])));
            h = fmaxf(h, 0.0f);
            a0 = fmaf(h, sW2[c*3+0], a0);
            a1 = fmaf(h, sW2[c*3+1], a1);
            a2 = fmaf(h, sW2[c*3+2], a2);
        }
#pragma unroll
        for (int off = 16; off; off >>= 1) {
            a0 += __shfl_xor_sync(0xffffffffu, a0, off);
            a1 += __shfl_xor_sync(0xffffffffu, a1, off);
            a2 += __shfl_xor_sync(0xffffffffu, a2, off);
        }
        if (lane == 0) {
            float v0 = a0 + b20, v1 = a1 + b21, v2 = a2 + b22;
            float d0 = v0 - (pmx - tmx), d1 = v1 - (pmy - tmy), d2 = v2 - (pmz - tmz);
            vacc += (double)(d0*d0) + (double)(d1*d1) + (double)(d2*d2);
            float xx = tmx + v0, xy = tmy + v1, xz = tmz + v2;
            float* o = &g_x1[(b*NSUB + p)*3];
            o[0] = xx; o[1] = xy; o[2] = xz;
            g_x1_sq[b*NSUB + p] = xx*xx + xy*xy + xz*xz;
        }
    }
    if (lane == 0) atomicAdd(&g_vel_sum, vacc);
}

__global__ void __launch_bounds__(512) k_otacc() {
    __shared__ double sred[512];
    int tid = threadIdx.x;
    double acc = 0.0;
    for (int i = tid; i < BATCH*NSUB; i += 512) {
        acc += (double)g_f1[i] + (double)g_g1[i];
        acc -= 0.5 * ((double)g_f2[i] + (double)g_g2[i]);
        acc -= 0.5 * ((double)g_f3[i] + (double)g_g3[i]);
    }
    sred[tid] = acc;
    __syncthreads();
    for (int s = 256; s; s >>= 1) {
        if (tid < s) sred[tid] += sred[tid + s];
        __syncthreads();
    }
    if (tid == 0) g_ot_sum = sred[0] / (double)(NSUB * BATCH);
}

__global__ void k_final(float* __restrict__ out) {
    float lv  = (float)(g_vel_sum / (double)(BATCH * NSUB * 3));
    float lot = (float)g_ot_sum;
    float lrg = (float)(g_reg_sum / (double)NSUB);
    out[0] = lv + 0.1f * lot + 0.01f * lrg;
    out[1] = lv;
    out[2] = lot;
    out[3] = lrg;
}

extern "C" void kernel_launch(void* const* d_in, const int* in_sizes, int n_in,
                              void* d_out, int out_size) {
    const float* target = (const float*)d_in[0];
    const float* t      = (const float*)d_in[1];
    const float* tmpl   = (const float*)d_in[2];
    const float* W_enc  = (const float*)d_in[3];
    const float* b_enc  = (const float*)d_in[4];
    const float* W1     = (const float*)d_in[5];
    const float* b1     = (const float*)d_in[6];
    const float* W2     = (const float*)d_in[7];
    const float* b2     = (const float*)d_in[8];
    float* out = (float*)d_out;

    float *p_tsub, *p_tsq, *p_tmsq, *p_lu, *p_lv, *p_x1, *p_x1sq;
    float *p_f1, *p_g1, *p_f2, *p_g2, *p_f3, *p_g3;
    cudaGetSymbolAddress((void**)&p_tsub, g_tsub);
    cudaGetSymbolAddress((void**)&p_tsq,  g_tsub_sq);
    cudaGetSymbolAddress((void**)&p_tmsq, g_tmpl_sq);
    cudaGetSymbolAddress((void**)&p_lu,   g_lu);
    cudaGetSymbolAddress((void**)&p_lv,   g_lv);
    cudaGetSymbolAddress((void**)&p_x1,   g_x1);
    cudaGetSymbolAddress((void**)&p_x1sq, g_x1_sq);
    cudaGetSymbolAddress((void**)&p_f1,   g_f1);
    cudaGetSymbolAddress((void**)&p_g1,   g_g1);
    cudaGetSymbolAddress((void**)&p_f2,   g_f2);
    cudaGetSymbolAddress((void**)&p_g2,   g_g2);
    cudaGetSymbolAddress((void**)&p_f3,   g_f3);
    cudaGetSymbolAddress((void**)&p_g3,   g_g3);

    const int SPB = NSUB*3, QB = NSUB;
    const float LOGN = -logf((float)NSUB);
    const float EPS = 0.0025f;
    const float CA  = -20.0f  * LOG2E_F;
    const float CO  = -200.0f * LOG2E_F;
    const float WM_A = LOG2E_F;
    const float WM_O = 400.0f * LOG2E_F;
    const float WA_O = LOGN * LOG2E_F;
    dim3 gL2(NSUB/32, BATCH, 2);

    k_init<<<1,1>>>();
    k_tmpl<<<NSUB/256,256>>>(tmpl);
    k_zero_all<<<(BATCH*NSUB)/256,256>>>();
    k_fps<<<BATCH*FPSC, 1024>>>(target);

    // Phase A: Sinkhorn assignment (z=0) fused with self-OT on tsub (z=1)
    for (int it = 0; it < 20; it++) {
        RunDesc a0 = { tmpl, p_tmsq, p_tsub, p_tsq, p_lv, p_lu,
                       0, 0, SPB, QB, WM_A, 0.0f, CA, -1.0f };
        RunDesc a1 = { p_tsub, p_tsq, p_tsub, p_tsq, p_g3, p_f3,
                       SPB, QB, SPB, QB, WM_O, WA_O, CO, -EPS };
        k_lse2<<<gL2,128>>>(a0, a1);
        RunDesc b0 = { p_tsub, p_tsq, tmpl, p_tmsq, p_lu, p_lv,
                       SPB, QB, 0, 0, WM_A, 0.0f, CA, -1.0f };
        RunDesc b1 = { p_tsub, p_tsq, p_tsub, p_tsq, p_f3, p_g3,
                       SPB, QB, SPB, QB, WM_O, WA_O, CO, -EPS };
        k_lse2<<<gL2,128>>>(b0, b1);
    }
    {
        dim3 gP(NSUB/32, BATCH);
        k_perm<<<gP,256>>>(tmpl);
        k_enc<<<BATCH,256>>>(W_enc, b_enc);
        k_bias<<<BATCH,256>>>(W1, b1, t);
        k_mlp<<<gP,256>>>(tmpl, W1, W2, b2, t);
    }
    // Phase B: OT(x1,tsub) (z=0) fused with self-OT(x1,x1) (z=1)
    for (int it = 0; it < 20; it++) {
        RunDesc a0 = { p_x1, p_x1sq, p_tsub, p_tsq, p_g1, p_f1,
                       SPB, QB, SPB, QB, WM_O, WA_O, CO, -EPS };
        RunDesc a1 = { p_x1, p_x1sq, p_x1, p_x1sq, p_g2, p_f2,
                       SPB, QB, SPB, QB, WM_O, WA_O, CO, -EPS };
        k_lse2<<<gL2,128>>>(a0, a1);
        RunDesc b0 = { p_tsub, p_tsq, p_x1, p_x1sq, p_f1, p_g1,
                       SPB, QB, SPB, QB, WM_O, WA_O, CO, -EPS };
        RunDesc b1 = { p_x1, p_x1sq, p_x1, p_x1sq, p_f2, p_g2,
                       SPB, QB, SPB, QB, WM_O, WA_O, CO, -EPS };
        k_lse2<<<gL2,128>>>(b0, b1);
    }
    k_otacc<<<1,512>>>();
    k_final<<<1,1>>>(out);
}

// round 15
// speedup vs baseline: 1.0147x; 1.0147x over previous
#include <cuda_runtime.h>
#include <math_constants.h>
#include <math.h>
#include <cstdint>

#define BATCH 8
#define NPTS 16384
#define NSUB 2048
#define DZ 256
#define DH 256
#define FPSC 8
#define PPC (NPTS/FPSC)
#define PPT (PPC/1024)

#define LOG2E_F 1.4426950408889634f
#define LN2_F   0.6931471805599453f

__device__ __forceinline__ float ex2(float x) {
    float y;
    asm("ex2.approx.ftz.f32 %0, %1;" : "=f"(y) : "f"(x));
    return y;
}

// ---- scratch (device globals; allocation is forbidden) ----
__device__ float g_tsub[BATCH*NSUB*3];
__device__ float g_tsub_sq[BATCH*NSUB];
__device__ float g_tmpl_sq[NSUB];
__device__ float g_lu[BATCH*NSUB];
__device__ float g_lv[BATCH*NSUB];
__device__ float g_perm[BATCH*NSUB*3];
__device__ float g_z[BATCH*DZ];
__device__ float g_bb[BATCH*DH];
__device__ float g_x1[BATCH*NSUB*3];
__device__ float g_x1_sq[BATCH*NSUB];
__device__ float g_f1[BATCH*NSUB];
__device__ float g_g1[BATCH*NSUB];
__device__ float g_f2[BATCH*NSUB];
__device__ float g_g2[BATCH*NSUB];
__device__ float g_f3[BATCH*NSUB];
__device__ float g_g3[BATCH*NSUB];
__device__ double g_vel_sum;
__device__ double g_ot_sum;
__device__ double g_reg_sum;

__global__ void k_init() { g_vel_sum = 0.0; g_ot_sum = 0.0; g_reg_sum = 0.0; }

__global__ void k_zero_all() {
    int i = blockIdx.x * blockDim.x + threadIdx.x;
    if (i < BATCH*NSUB) {
        g_lu[i] = 0.f; g_lv[i] = 0.f;
        g_f1[i] = 0.f; g_g1[i] = 0.f;
        g_f2[i] = 0.f; g_g2[i] = 0.f;
        g_f3[i] = 0.f; g_g3[i] = 0.f;
    }
}

__global__ void k_tmpl(const float* __restrict__ tmpl) {
    __shared__ double sred[256];
    int n = blockIdx.x * 256 + threadIdx.x;
    float tx = tmpl[n*3+0], ty = tmpl[n*3+1], tz = tmpl[n*3+2];
    float sq = tx*tx + ty*ty + tz*tz;
    g_tmpl_sq[n] = sq;
    float d = sqrtf(sq) - 1.0f;
    sred[threadIdx.x] = (double)(d * d);
    __syncthreads();
    for (int s = 128; s; s >>= 1) {
        if (threadIdx.x < s) sred[threadIdx.x] += sred[threadIdx.x + s];
        __syncthreads();
    }
    if (threadIdx.x == 0) atomicAdd(&g_reg_sum, sred[0]);
}

// ---------------- FPS over an 8-CTA cluster per batch (known good, R13) ----------------
__device__ __forceinline__ void st_cluster_f4(unsigned int saddr, unsigned int rank, float4 v) {
    unsigned int ra;
    asm volatile("mapa.shared::cluster.u32 %0, %1, %2;" : "=r"(ra) : "r"(saddr), "r"(rank));
    asm volatile("st.shared::cluster.v4.f32 [%0], {%1,%2,%3,%4};"
                 :: "r"(ra), "f"(v.x), "f"(v.y), "f"(v.z), "f"(v.w) : "memory");
}
__device__ __forceinline__ void st_cluster_i32(unsigned int saddr, unsigned int rank, int v) {
    unsigned int ra;
    asm volatile("mapa.shared::cluster.u32 %0, %1, %2;" : "=r"(ra) : "r"(saddr), "r"(rank));
    asm volatile("st.shared::cluster.b32 [%0], %1;" :: "r"(ra), "r"(v) : "memory");
}
#define CLUSTER_SYNC_() do { \
    asm volatile("barrier.cluster.arrive.aligned;" ::: "memory"); \
    asm volatile("barrier.cluster.wait.aligned;" ::: "memory"); } while (0)

__global__ void __launch_bounds__(1024) __cluster_dims__(FPSC, 1, 1)
k_fps(const float* __restrict__ target) {
    __shared__ float ys[PPC], zs[PPC];
    __shared__ float rv[32]; __shared__ int ri[32];
    __shared__ float4 s_mb[2][FPSC]; __shared__ int s_mbi[2][FPSC];
    __shared__ float4 s_cand; __shared__ float s_bv; __shared__ int s_bi;
    int tid = threadIdx.x;
    unsigned int rank;
    asm("mov.u32 %0, %%cluster_ctarank;" : "=r"(rank));
    int b = blockIdx.x / FPSC;
    int base = (int)rank * PPC;
    const float* tg = target + (size_t)b * NPTS * 3 + (size_t)base * 3;
    float rx[PPT], dist[PPT];
#pragma unroll
    for (int j = 0; j < PPT; j++) {
        int n = tid + j * 1024;
        rx[j] = tg[n*3+0];
        ys[n] = tg[n*3+1];
        zs[n] = tg[n*3+2];
        dist[j] = CUDART_INF_F;
    }
    __syncthreads();
    if (tid == 0) {
        float4 c = (rank == 0) ? make_float4(rx[0], ys[0], zs[0], 1.0f)
                               : make_float4(0.f, 0.f, 0.f, -1.0f);
        unsigned int a4 = (unsigned int)__cvta_generic_to_shared(&s_mb[0][rank]);
        unsigned int ai = (unsigned int)__cvta_generic_to_shared(&s_mbi[0][rank]);
        for (unsigned int r = 0; r < FPSC; r++) {
            st_cluster_f4(a4, r, c);
            st_cluster_i32(ai, r, (rank == 0) ? 0 : base);
        }
    }
    CLUSTER_SYNC_();
    int par = 0;
    for (int i = 0; i < NSUB; i++) {
        float bvw = -CUDART_INF_F; int biw = 0x7fffffff;
        float cx = 0.f, cy = 0.f, cz = 0.f;
#pragma unroll
        for (int r = 0; r < FPSC; r++) {
            float4 c = s_mb[par][r]; int ci = s_mbi[par][r];
            if (c.w > bvw || (c.w == bvw && ci < biw)) {
                bvw = c.w; biw = ci; cx = c.x; cy = c.y; cz = c.z;
            }
        }
        if (rank == 0 && tid == 0) {
            float* o = &g_tsub[(b*NSUB + i)*3];
            o[0] = cx; o[1] = cy; o[2] = cz;
            g_tsub_sq[b*NSUB + i] = cx*cx + cy*cy + cz*cz;
        }
        float bv = -1.0f; int bi = base;
#pragma unroll
        for (int j = 0; j < PPT; j++) {
            int n = tid + j * 1024;
            float dx = __fadd_rn(rx[j], -cx);
            float dy = __fadd_rn(ys[n], -cy);
            float dz = __fadd_rn(zs[n], -cz);
            float d  = __fadd_rn(__fadd_rn(__fmul_rn(dx,dx), __fmul_rn(dy,dy)), __fmul_rn(dz,dz));
            float nd = fminf(dist[j], d);
            dist[j] = nd;
            if (nd > bv) { bv = nd; bi = base + n; }
        }
#pragma unroll
        for (int off = 16; off; off >>= 1) {
            float ov = __shfl_xor_sync(0xffffffffu, bv, off);
            int   oi = __shfl_xor_sync(0xffffffffu, bi, off);
            if (ov > bv || (ov == bv && oi < bi)) { bv = ov; bi = oi; }
        }
        if ((tid & 31) == 0) { rv[tid >> 5] = bv; ri[tid >> 5] = bi; }
        __syncthreads();
        if (tid < 32) {
            bv = rv[tid]; bi = ri[tid];
#pragma unroll
            for (int off = 16; off; off >>= 1) {
                float ov = __shfl_xor_sync(0xffffffffu, bv, off);
                int   oi = __shfl_xor_sync(0xffffffffu, bi, off);
                if (ov > bv || (ov == bv && oi < bi)) { bv = ov; bi = oi; }
            }
            if (tid == 0) { s_bv = bv; s_bi = bi; }
        }
        __syncthreads();
        int wbi = s_bi;
        int loc = wbi - base;
        if ((loc & 1023) == tid) {
            int j = loc >> 10;
            float x = (j == 0) ? rx[0] : rx[PPT-1];
            s_cand = make_float4(x, ys[loc], zs[loc], s_bv);
        }
        __syncthreads();
        if (tid < FPSC) {
            unsigned int a4 = (unsigned int)__cvta_generic_to_shared(&s_mb[par^1][rank]);
            unsigned int ai = (unsigned int)__cvta_generic_to_shared(&s_mbi[par^1][rank]);
            st_cluster_f4(a4, (unsigned int)tid, s_cand);
            st_cluster_i32(ai, (unsigned int)tid, wbi);
        }
        CLUSTER_SYNC_();
        par ^= 1;
    }
}

struct RunDesc {
    const float *aPts, *aSq, *bPts, *bSq, *w;
    float *out;
    int aPB, aSB, bPB, bSB;
    float wMul, wAdd, coeff, outScale;  // log2-domain
};

// Per-(q,m) LSE step: identical arithmetic to R13 (bit-exact).
#define LSE_STEP(q, pbv)                                                     \
    {                                                                        \
        float arg = fmaf(ax[q], (pbv).x,                                     \
                    fmaf(ay[q], (pbv).y, fmaf(az[q], (pbv).z, (pbv).w)));    \
        float diff = arg - mr[q];                                            \
        float nm = fmaxf(mr[q], arg);                                        \
        float e  = ex2(-fabsf(diff));                                        \
        bool  gt = diff > 0.0f;                                              \
        sr[q] = fmaf(sr[q], gt ? e : 1.0f, gt ? 1.0f : e);                   \
        mr[q] = nm;                                                          \
    }

// out[b][r] = outScale * ln-LSE_m(...); log2-domain args; online per-row max;
// software-pipelined LDS (prefetch next column while computing current).
__global__ void __launch_bounds__(256) k_lse2(RunDesc d0, RunDesc d1) {
    __shared__ float4 sB[NSUB];
    RunDesc d = (blockIdx.z == 0) ? d0 : d1;
    int b = blockIdx.y, tid = threadIdx.x;
    float coeff = d.coeff;
    float s = -2.0f * coeff;
    for (int m = tid; m < NSUB; m += 256) {
        const float* bp = d.bPts + b*d.bPB + m*3;
        float wv = fmaf(d.w[b*NSUB + m], d.wMul, d.wAdd);
        wv = fmaf(d.bSq[b*d.bSB + m], coeff, wv);
        sB[m] = make_float4(s*bp[0], s*bp[1], s*bp[2], wv);
    }
    __syncthreads();
    int warp = tid >> 5, lane = tid & 31;
    int r0 = blockIdx.x * 32 + warp * 4;
    float ax[4], ay[4], az[4], A[4], mr[4], sr[4];
#pragma unroll
    for (int q = 0; q < 4; q++) {
        const float* ap = d.aPts + b*d.aPB + (r0 + q)*3;
        ax[q] = ap[0]; ay[q] = ap[1]; az[q] = ap[2];
        A[q] = coeff * d.aSq[b*d.aSB + r0 + q];
        mr[q] = -CUDART_INF_F; sr[q] = 0.f;
    }
    // pipelined m-loop: 64 trips, peel last
    float4 pb = sB[lane];
    int m = lane;
#pragma unroll 4
    for (int it = 0; it < 63; it++) {
        float4 nx = sB[m + 32];
        LSE_STEP(0, pb); LSE_STEP(1, pb); LSE_STEP(2, pb); LSE_STEP(3, pb);
        pb = nx; m += 32;
    }
    LSE_STEP(0, pb); LSE_STEP(1, pb); LSE_STEP(2, pb); LSE_STEP(3, pb);
#pragma unroll
    for (int q = 0; q < 4; q++) {
#pragma unroll
        for (int off = 16; off; off >>= 1) {
            float om = __shfl_xor_sync(0xffffffffu, mr[q], off);
            float os = __shfl_xor_sync(0xffffffffu, sr[q], off);
            float nm = fmaxf(mr[q], om);
            sr[q] = fmaf(sr[q], ex2(mr[q]-nm), os * ex2(om-nm));
            mr[q] = nm;
        }
    }
    if (lane == 0) {
#pragma unroll
        for (int q = 0; q < 4; q++) {
            float lse = fmaf(mr[q] + A[q], LN2_F, logf(sr[q]));
            d.out[b*NSUB + r0 + q] = d.outScale * lse;
        }
    }
}

// target_perm = P @ target_sub; log2-domain args. (known good, R13)
__global__ void __launch_bounds__(256) k_perm(const float* __restrict__ tmpl) {
    __shared__ float4 sB[NSUB];
    int b = blockIdx.y, tid = threadIdx.x;
    const float coeff = -20.0f * LOG2E_F;
    const float s = 40.0f * LOG2E_F;
    const float inv_s = 1.0f / (40.0f * LOG2E_F);
    for (int m = tid; m < NSUB; m += 256) {
        const float* bp = &g_tsub[(b*NSUB + m)*3];
        float wv = fmaf(g_tsub_sq[b*NSUB + m], coeff, g_lv[b*NSUB + m] * LOG2E_F);
        sB[m] = make_float4(s*bp[0], s*bp[1], s*bp[2], wv);
    }
    __syncthreads();
    int warp = tid >> 5, lane = tid & 31;
    int r0 = blockIdx.x * 32 + warp * 4;
    float ax[4], ay[4], az[4], C[4], px[4], py[4], pz[4];
#pragma unroll
    for (int q = 0; q < 4; q++) {
        const float* ap = &tmpl[(r0 + q)*3];
        ax[q] = ap[0]; ay[q] = ap[1]; az[q] = ap[2];
        C[q] = fmaf(g_tmpl_sq[r0 + q], coeff, g_lu[b*NSUB + r0 + q] * LOG2E_F);
        px[q] = 0.f; py[q] = 0.f; pz[q] = 0.f;
    }
    for (int m = lane; m < NSUB; m += 32) {
        float4 pb = sB[m];
#pragma unroll
        for (int q = 0; q < 4; q++) {
            float arg = fmaf(ax[q], pb.x, fmaf(ay[q], pb.y, fmaf(az[q], pb.z, pb.w)));
            float e = ex2(arg + C[q]);
            px[q] = fmaf(e, pb.x, px[q]);
            py[q] = fmaf(e, pb.y, py[q]);
            pz[q] = fmaf(e, pb.z, pz[q]);
        }
    }
#pragma unroll
    for (int q = 0; q < 4; q++) {
#pragma unroll
        for (int off = 16; off; off >>= 1) {
            px[q] += __shfl_xor_sync(0xffffffffu, px[q], off);
            py[q] += __shfl_xor_sync(0xffffffffu, py[q], off);
            pz[q] += __shfl_xor_sync(0xffffffffu, pz[q], off);
        }
    }
    if (lane == 0) {
#pragma unroll
        for (int q = 0; q < 4; q++) {
            float* o = &g_perm[(b*NSUB + r0 + q)*3];
            o[0] = px[q] * inv_s; o[1] = py[q] * inv_s; o[2] = pz[q] * inv_s;
        }
    }
}

__global__ void __launch_bounds__(256) k_enc(const float* __restrict__ W, const float* __restrict__ be) {
    __shared__ float sP[NSUB*3];
    int b = blockIdx.x, tid = threadIdx.x;
    for (int i = tid; i < NSUB*3; i += 256) sP[i] = g_tsub[b*NSUB*3 + i];
    __syncthreads();
    float wx = W[tid], wy = W[256 + tid], wz = W[512 + tid], bb = be[tid];
    float zm = 0.0f;
    for (int m = 0; m < NSUB; m++) {
        float v = fmaf(sP[m*3], wx, fmaf(sP[m*3+1], wy, fmaf(sP[m*3+2], wz, bb)));
        zm = fmaxf(zm, fmaxf(v, 0.0f));
    }
    g_z[b*DZ + tid] = zm;
}

__global__ void __launch_bounds__(256) k_bias(const float* __restrict__ W1, const float* __restrict__ b1,
                                              const float* __restrict__ t) {
    __shared__ float sZ[DZ];
    int b = blockIdx.x, c = threadIdx.x;
    sZ[c] = g_z[b*DZ + c];
    __syncthreads();
    float tc = fminf(fmaxf(t[b], 1e-5f), 1.0f - 1e-5f);
    float acc = fmaf(tc, W1[3*DH + c], b1[c]);
    for (int k = 0; k < DZ; k++)
        acc = fmaf(sZ[k], W1[(4 + k)*DH + c], acc);
    g_bb[b*DH + c] = acc;
}

__global__ void __launch_bounds__(256) k_mlp(const float* __restrict__ tmpl, const float* __restrict__ W1,
                                             const float* __restrict__ W2, const float* __restrict__ b2,
                                             const float* __restrict__ t) {
    __shared__ float sBB[DH], sWa[DH], sWb[DH], sWc[DH], sW2[DH*3];
    int b = blockIdx.y, tid = threadIdx.x;
    sBB[tid] = g_bb[b*DH + tid];
    sWa[tid] = W1[0*DH + tid];
    sWb[tid] = W1[1*DH + tid];
    sWc[tid] = W1[2*DH + tid];
    for (int i = tid; i < DH*3; i += 256) sW2[i] = W2[i];
    __syncthreads();
    int warp = tid >> 5, lane = tid & 31;
    float tc = fminf(fmaxf(t[b], 1e-5f), 1.0f - 1e-5f);
    float u = 1.0f - tc;
    float b20 = b2[0], b21 = b2[1], b22 = b2[2];
    double vacc = 0.0;
    for (int q = 0; q < 4; q++) {
        int p = blockIdx.x * 32 + warp * 4 + q;
        float tmx = tmpl[p*3], tmy = tmpl[p*3+1], tmz = tmpl[p*3+2];
        const float* pp = &g_perm[(b*NSUB + p)*3];
        float pmx = pp[0], pmy = pp[1], pmz = pp[2];
        float x0 = u*tmx + tc*pmx, x1 = u*tmy + tc*pmy, x2 = u*tmz + tc*pmz;
        float a0 = 0.f, a1 = 0.f, a2 = 0.f;
#pragma unroll
        for (int k = 0; k < 8; k++) {
            int c = lane + k*32;
            float h = fmaf(x0, sWa[c], fmaf(x1, sWb[c], fmaf(x2, sWc[c], sBB[c])));
            h = fmaxf(h, 0.0f);
            a0 = fmaf(h, sW2[c*3+0], a0);
            a1 = fmaf(h, sW2[c*3+1], a1);
            a2 = fmaf(h, sW2[c*3+2], a2);
        }
#pragma unroll
        for (int off = 16; off; off >>= 1) {
            a0 += __shfl_xor_sync(0xffffffffu, a0, off);
            a1 += __shfl_xor_sync(0xffffffffu, a1, off);
            a2 += __shfl_xor_sync(0xffffffffu, a2, off);
        }
        if (lane == 0) {
            float v0 = a0 + b20, v1 = a1 + b21, v2 = a2 + b22;
            float d0 = v0 - (pmx - tmx), d1 = v1 - (pmy - tmy), d2 = v2 - (pmz - tmz);
            vacc += (double)(d0*d0) + (double)(d1*d1) + (double)(d2*d2);
            float xx = tmx + v0, xy = tmy + v1, xz = tmz + v2;
            float* o = &g_x1[(b*NSUB + p)*3];
            o[0] = xx; o[1] = xy; o[2] = xz;
            g_x1_sq[b*NSUB + p] = xx*xx + xy*xy + xz*xz;
        }
    }
    if (lane == 0) atomicAdd(&g_vel_sum, vacc);
}

__global__ void __launch_bounds__(512) k_otacc() {
    __shared__ double sred[512];
    int tid = threadIdx.x;
    double acc = 0.0;
    for (int i = tid; i < BATCH*NSUB; i += 512) {
        acc += (double)g_f1[i] + (double)g_g1[i];
        acc -= 0.5 * ((double)g_f2[i] + (double)g_g2[i]);
        acc -= 0.5 * ((double)g_f3[i] + (double)g_g3[i]);
    }
    sred[tid] = acc;
    __syncthreads();
    for (int s = 256; s; s >>= 1) {
        if (tid < s) sred[tid] += sred[tid + s];
        __syncthreads();
    }
    if (tid == 0) g_ot_sum = sred[0] / (double)(NSUB * BATCH);
}

__global__ void k_final(float* __restrict__ out) {
    float lv  = (float)(g_vel_sum / (double)(BATCH * NSUB * 3));
    float lot = (float)g_ot_sum;
    float lrg = (float)(g_reg_sum / (double)NSUB);
    out[0] = lv + 0.1f * lot + 0.01f * lrg;
    out[1] = lv;
    out[2] = lot;
    out[3] = lrg;
}

extern "C" void kernel_launch(void* const* d_in, const int* in_sizes, int n_in,
                              void* d_out, int out_size) {
    const float* target = (const float*)d_in[0];
    const float* t      = (const float*)d_in[1];
    const float* tmpl   = (const float*)d_in[2];
    const float* W_enc  = (const float*)d_in[3];
    const float* b_enc  = (const float*)d_in[4];
    const float* W1     = (const float*)d_in[5];
    const float* b1     = (const float*)d_in[6];
    const float* W2     = (const float*)d_in[7];
    const float* b2     = (const float*)d_in[8];
    float* out = (float*)d_out;

    float *p_tsub, *p_tsq, *p_tmsq, *p_lu, *p_lv, *p_x1, *p_x1sq;
    float *p_f1, *p_g1, *p_f2, *p_g2, *p_f3, *p_g3;
    cudaGetSymbolAddress((void**)&p_tsub, g_tsub);
    cudaGetSymbolAddress((void**)&p_tsq,  g_tsub_sq);
    cudaGetSymbolAddress((void**)&p_tmsq, g_tmpl_sq);
    cudaGetSymbolAddress((void**)&p_lu,   g_lu);
    cudaGetSymbolAddress((void**)&p_lv,   g_lv);
    cudaGetSymbolAddress((void**)&p_x1,   g_x1);
    cudaGetSymbolAddress((void**)&p_x1sq, g_x1_sq);
    cudaGetSymbolAddress((void**)&p_f1,   g_f1);
    cudaGetSymbolAddress((void**)&p_g1,   g_g1);
    cudaGetSymbolAddress((void**)&p_f2,   g_f2);
    cudaGetSymbolAddress((void**)&p_g2,   g_g2);
    cudaGetSymbolAddress((void**)&p_f3,   g_f3);
    cudaGetSymbolAddress((void**)&p_g3,   g_g3);

    const int SPB = NSUB*3, QB = NSUB;
    const float LOGN = -logf((float)NSUB);
    const float EPS = 0.0025f;
    const float CA  = -20.0f  * LOG2E_F;
    const float CO  = -200.0f * LOG2E_F;
    const float WM_A = LOG2E_F;
    const float WM_O = 400.0f * LOG2E_F;
    const float WA_O = LOGN * LOG2E_F;
    dim3 gL2(NSUB/32, BATCH, 2);

    k_init<<<1,1>>>();
    k_tmpl<<<NSUB/256,256>>>(tmpl);
    k_zero_all<<<(BATCH*NSUB)/256,256>>>();
    k_fps<<<BATCH*FPSC, 1024>>>(target);

    // Phase A: Sinkhorn assignment (z=0) fused with self-OT on tsub (z=1)
    for (int it = 0; it < 20; it++) {
        RunDesc a0 = { tmpl, p_tmsq, p_tsub, p_tsq, p_lv, p_lu,
                       0, 0, SPB, QB, WM_A, 0.0f, CA, -1.0f };
        RunDesc a1 = { p_tsub, p_tsq, p_tsub, p_tsq, p_g3, p_f3,
                       SPB, QB, SPB, QB, WM_O, WA_O, CO, -EPS };
        k_lse2<<<gL2,256>>>(a0, a1);
        RunDesc b0 = { p_tsub, p_tsq, tmpl, p_tmsq, p_lu, p_lv,
                       SPB, QB, 0, 0, WM_A, 0.0f, CA, -1.0f };
        RunDesc b1 = { p_tsub, p_tsq, p_tsub, p_tsq, p_f3, p_g3,
                       SPB, QB, SPB, QB, WM_O, WA_O, CO, -EPS };
        k_lse2<<<gL2,256>>>(b0, b1);
    }
    {
        dim3 gP(NSUB/32, BATCH);
        k_perm<<<gP,256>>>(tmpl);
        k_enc<<<BATCH,256>>>(W_enc, b_enc);
        k_bias<<<BATCH,256>>>(W1, b1, t);
        k_mlp<<<gP,256>>>(tmpl, W1, W2, b2, t);
    }
    // Phase B: OT(x1,tsub) (z=0) fused with self-OT(x1,x1) (z=1)
    for (int it = 0; it < 20; it++) {
        RunDesc a0 = { p_x1, p_x1sq, p_tsub, p_tsq, p_g1, p_f1,
                       SPB, QB, SPB, QB, WM_O, WA_O, CO, -EPS };
        RunDesc a1 = { p_x1, p_x1sq, p_x1, p_x1sq, p_g2, p_f2,
                       SPB, QB, SPB, QB, WM_O, WA_O, CO, -EPS };
        k_lse2<<<gL2,256>>>(a0, a1);
        RunDesc b0 = { p_tsub, p_tsq, p_x1, p_x1sq, p_f1, p_g1,
                       SPB, QB, SPB, QB, WM_O, WA_O, CO, -EPS };
        RunDesc b1 = { p_x1, p_x1sq, p_x1, p_x1sq, p_f2, p_g2,
                       SPB, QB, SPB, QB, WM_O, WA_O, CO, -EPS };
        k_lse2<<<gL2,256>>>(b0, b1);
    }
    k_otacc<<<1,512>>>();
    k_final<<<1,1>>>(out);
}

// round 16
// speedup vs baseline: 1.1142x; 1.0981x over previous
#include <cuda_runtime.h>
#include <math_constants.h>
#include <math.h>
#include <cstdint>

#define BATCH 8
#define NPTS 16384
#define NSUB 2048
#define DZ 256
#define DH 256
#define FPSC 8
#define PPC (NPTS/FPSC)
#define PPT (PPC/1024)

#define LOG2E_F 1.4426950408889634f
#define LN2_F   0.6931471805599453f

__device__ __forceinline__ float ex2(float x) {
    float y;
    asm("ex2.approx.ftz.f32 %0, %1;" : "=f"(y) : "f"(x));
    return y;
}

// ---- scratch (device globals; allocation is forbidden) ----
__device__ float g_tsub[BATCH*NSUB*3];
__device__ float g_tsub_sq[BATCH*NSUB];
__device__ float g_tmpl_sq[NSUB];
__device__ float g_lu[BATCH*NSUB];
__device__ float g_lv[BATCH*NSUB];
__device__ float g_perm[BATCH*NSUB*3];
__device__ float g_z[BATCH*DZ];
__device__ float g_bb[BATCH*DH];
__device__ float g_x1[BATCH*NSUB*3];
__device__ float g_x1_sq[BATCH*NSUB];
__device__ float g_f1[BATCH*NSUB];
__device__ float g_g1[BATCH*NSUB];
__device__ float g_f2[BATCH*NSUB];
__device__ float g_g2[BATCH*NSUB];
__device__ float g_f3[BATCH*NSUB];
__device__ float g_g3[BATCH*NSUB];
__device__ double g_vel_sum;
__device__ double g_ot_sum;
__device__ double g_reg_sum;

__global__ void k_init() { g_vel_sum = 0.0; g_ot_sum = 0.0; g_reg_sum = 0.0; }

__global__ void k_zero_all() {
    int i = blockIdx.x * blockDim.x + threadIdx.x;
    if (i < BATCH*NSUB) {
        g_lu[i] = 0.f; g_lv[i] = 0.f;
        g_f1[i] = 0.f; g_g1[i] = 0.f;
        g_f2[i] = 0.f; g_g2[i] = 0.f;
        g_f3[i] = 0.f; g_g3[i] = 0.f;
    }
}

__global__ void k_tmpl(const float* __restrict__ tmpl) {
    __shared__ double sred[256];
    int n = blockIdx.x * 256 + threadIdx.x;
    float tx = tmpl[n*3+0], ty = tmpl[n*3+1], tz = tmpl[n*3+2];
    float sq = tx*tx + ty*ty + tz*tz;
    g_tmpl_sq[n] = sq;
    float d = sqrtf(sq) - 1.0f;
    sred[threadIdx.x] = (double)(d * d);
    __syncthreads();
    for (int s = 128; s; s >>= 1) {
        if (threadIdx.x < s) sred[threadIdx.x] += sred[threadIdx.x + s];
        __syncthreads();
    }
    if (threadIdx.x == 0) atomicAdd(&g_reg_sum, sred[0]);
}

// ---------------- FPS over an 8-CTA cluster per batch (known good, R13) ----------------
__device__ __forceinline__ void st_cluster_f4(unsigned int saddr, unsigned int rank, float4 v) {
    unsigned int ra;
    asm volatile("mapa.shared::cluster.u32 %0, %1, %2;" : "=r"(ra) : "r"(saddr), "r"(rank));
    asm volatile("st.shared::cluster.v4.f32 [%0], {%1,%2,%3,%4};"
                 :: "r"(ra), "f"(v.x), "f"(v.y), "f"(v.z), "f"(v.w) : "memory");
}
__device__ __forceinline__ void st_cluster_i32(unsigned int saddr, unsigned int rank, int v) {
    unsigned int ra;
    asm volatile("mapa.shared::cluster.u32 %0, %1, %2;" : "=r"(ra) : "r"(saddr), "r"(rank));
    asm volatile("st.shared::cluster.b32 [%0], %1;" :: "r"(ra), "r"(v) : "memory");
}
#define CLUSTER_SYNC_() do { \
    asm volatile("barrier.cluster.arrive.aligned;" ::: "memory"); \
    asm volatile("barrier.cluster.wait.aligned;" ::: "memory"); } while (0)

__global__ void __launch_bounds__(1024) __cluster_dims__(FPSC, 1, 1)
k_fps(const float* __restrict__ target) {
    __shared__ float ys[PPC], zs[PPC];
    __shared__ float rv[32]; __shared__ int ri[32];
    __shared__ float4 s_mb[2][FPSC]; __shared__ int s_mbi[2][FPSC];
    __shared__ float4 s_cand; __shared__ float s_bv; __shared__ int s_bi;
    int tid = threadIdx.x;
    unsigned int rank;
    asm("mov.u32 %0, %%cluster_ctarank;" : "=r"(rank));
    int b = blockIdx.x / FPSC;
    int base = (int)rank * PPC;
    const float* tg = target + (size_t)b * NPTS * 3 + (size_t)base * 3;
    float rx[PPT], dist[PPT];
#pragma unroll
    for (int j = 0; j < PPT; j++) {
        int n = tid + j * 1024;
        rx[j] = tg[n*3+0];
        ys[n] = tg[n*3+1];
        zs[n] = tg[n*3+2];
        dist[j] = CUDART_INF_F;
    }
    __syncthreads();
    if (tid == 0) {
        float4 c = (rank == 0) ? make_float4(rx[0], ys[0], zs[0], 1.0f)
                               : make_float4(0.f, 0.f, 0.f, -1.0f);
        unsigned int a4 = (unsigned int)__cvta_generic_to_shared(&s_mb[0][rank]);
        unsigned int ai = (unsigned int)__cvta_generic_to_shared(&s_mbi[0][rank]);
        for (unsigned int r = 0; r < FPSC; r++) {
            st_cluster_f4(a4, r, c);
            st_cluster_i32(ai, r, (rank == 0) ? 0 : base);
        }
    }
    CLUSTER_SYNC_();
    int par = 0;
    for (int i = 0; i < NSUB; i++) {
        float bvw = -CUDART_INF_F; int biw = 0x7fffffff;
        float cx = 0.f, cy = 0.f, cz = 0.f;
#pragma unroll
        for (int r = 0; r < FPSC; r++) {
            float4 c = s_mb[par][r]; int ci = s_mbi[par][r];
            if (c.w > bvw || (c.w == bvw && ci < biw)) {
                bvw = c.w; biw = ci; cx = c.x; cy = c.y; cz = c.z;
            }
        }
        if (rank == 0 && tid == 0) {
            float* o = &g_tsub[(b*NSUB + i)*3];
            o[0] = cx; o[1] = cy; o[2] = cz;
            g_tsub_sq[b*NSUB + i] = cx*cx + cy*cy + cz*cz;
        }
        float bv = -1.0f; int bi = base;
#pragma unroll
        for (int j = 0; j < PPT; j++) {
            int n = tid + j * 1024;
            float dx = __fadd_rn(rx[j], -cx);
            float dy = __fadd_rn(ys[n], -cy);
            float dz = __fadd_rn(zs[n], -cz);
            float d  = __fadd_rn(__fadd_rn(__fmul_rn(dx,dx), __fmul_rn(dy,dy)), __fmul_rn(dz,dz));
            float nd = fminf(dist[j], d);
            dist[j] = nd;
            if (nd > bv) { bv = nd; bi = base + n; }
        }
#pragma unroll
        for (int off = 16; off; off >>= 1) {
            float ov = __shfl_xor_sync(0xffffffffu, bv, off);
            int   oi = __shfl_xor_sync(0xffffffffu, bi, off);
            if (ov > bv || (ov == bv && oi < bi)) { bv = ov; bi = oi; }
        }
        if ((tid & 31) == 0) { rv[tid >> 5] = bv; ri[tid >> 5] = bi; }
        __syncthreads();
        if (tid < 32) {
            bv = rv[tid]; bi = ri[tid];
#pragma unroll
            for (int off = 16; off; off >>= 1) {
                float ov = __shfl_xor_sync(0xffffffffu, bv, off);
                int   oi = __shfl_xor_sync(0xffffffffu, bi, off);
                if (ov > bv || (ov == bv && oi < bi)) { bv = ov; bi = oi; }
            }
            if (tid == 0) { s_bv = bv; s_bi = bi; }
        }
        __syncthreads();
        int wbi = s_bi;
        int loc = wbi - base;
        if ((loc & 1023) == tid) {
            int j = loc >> 10;
            float x = (j == 0) ? rx[0] : rx[PPT-1];
            s_cand = make_float4(x, ys[loc], zs[loc], s_bv);
        }
        __syncthreads();
        if (tid < FPSC) {
            unsigned int a4 = (unsigned int)__cvta_generic_to_shared(&s_mb[par^1][rank]);
            unsigned int ai = (unsigned int)__cvta_generic_to_shared(&s_mbi[par^1][rank]);
            st_cluster_f4(a4, (unsigned int)tid, s_cand);
            st_cluster_i32(ai, (unsigned int)tid, wbi);
        }
        CLUSTER_SYNC_();
        par ^= 1;
    }
}

struct RunDesc {
    const float *aPts, *aSq, *bPts, *bSq, *w;
    float *out;
    int aPB, aSB, bPB, bSB;
    float wMul, wAdd, coeff, outScale;  // log2-domain
};

// out[b][r] = outScale * ln-LSE_m(...); log2-domain args; CHUNKED max:
// per trip each lane handles m, m+32, m+64, m+96; one rescale per chunk of 4.
__global__ void __launch_bounds__(256) k_lse2(RunDesc d0, RunDesc d1) {
    __shared__ float4 sB[NSUB];
    RunDesc d = (blockIdx.z == 0) ? d0 : d1;
    int b = blockIdx.y, tid = threadIdx.x;
    float coeff = d.coeff;
    float s = -2.0f * coeff;
    for (int m = tid; m < NSUB; m += 256) {
        const float* bp = d.bPts + b*d.bPB + m*3;
        float wv = fmaf(d.w[b*NSUB + m], d.wMul, d.wAdd);
        wv = fmaf(d.bSq[b*d.bSB + m], coeff, wv);
        sB[m] = make_float4(s*bp[0], s*bp[1], s*bp[2], wv);
    }
    __syncthreads();
    int warp = tid >> 5, lane = tid & 31;
    int r0 = blockIdx.x * 32 + warp * 4;
    float ax[4], ay[4], az[4], A[4], mr[4], sr[4];
#pragma unroll
    for (int q = 0; q < 4; q++) {
        const float* ap = d.aPts + b*d.aPB + (r0 + q)*3;
        ax[q] = ap[0]; ay[q] = ap[1]; az[q] = ap[2];
        A[q] = coeff * d.aSq[b*d.aSB + r0 + q];
        mr[q] = -CUDART_INF_F; sr[q] = 0.f;
    }
#pragma unroll 2
    for (int m0 = lane; m0 < NSUB; m0 += 128) {
        float4 p0 = sB[m0];
        float4 p1 = sB[m0 + 32];
        float4 p2 = sB[m0 + 64];
        float4 p3 = sB[m0 + 96];
#pragma unroll
        for (int q = 0; q < 4; q++) {
            float a0 = fmaf(ax[q], p0.x, fmaf(ay[q], p0.y, fmaf(az[q], p0.z, p0.w)));
            float a1 = fmaf(ax[q], p1.x, fmaf(ay[q], p1.y, fmaf(az[q], p1.z, p1.w)));
            float a2 = fmaf(ax[q], p2.x, fmaf(ay[q], p2.y, fmaf(az[q], p2.z, p2.w)));
            float a3 = fmaf(ax[q], p3.x, fmaf(ay[q], p3.y, fmaf(az[q], p3.z, p3.w)));
            float cm = fmaxf(fmaxf(a0, a1), fmaxf(a2, a3));
            float nm = fmaxf(mr[q], cm);
            float cs = (ex2(a0 - nm) + ex2(a1 - nm)) + (ex2(a2 - nm) + ex2(a3 - nm));
            sr[q] = fmaf(sr[q], ex2(mr[q] - nm), cs);
            mr[q] = nm;
        }
    }
#pragma unroll
    for (int q = 0; q < 4; q++) {
#pragma unroll
        for (int off = 16; off; off >>= 1) {
            float om = __shfl_xor_sync(0xffffffffu, mr[q], off);
            float os = __shfl_xor_sync(0xffffffffu, sr[q], off);
            float nm = fmaxf(mr[q], om);
            sr[q] = fmaf(sr[q], ex2(mr[q]-nm), os * ex2(om-nm));
            mr[q] = nm;
        }
    }
    if (lane == 0) {
#pragma unroll
        for (int q = 0; q < 4; q++) {
            float lse = fmaf(mr[q] + A[q], LN2_F, logf(sr[q]));
            d.out[b*NSUB + r0 + q] = d.outScale * lse;
        }
    }
}

// target_perm = P @ target_sub; log2-domain args. (known good, R13)
__global__ void __launch_bounds__(256) k_perm(const float* __restrict__ tmpl) {
    __shared__ float4 sB[NSUB];
    int b = blockIdx.y, tid = threadIdx.x;
    const float coeff = -20.0f * LOG2E_F;
    const float s = 40.0f * LOG2E_F;
    const float inv_s = 1.0f / (40.0f * LOG2E_F);
    for (int m = tid; m < NSUB; m += 256) {
        const float* bp = &g_tsub[(b*NSUB + m)*3];
        float wv = fmaf(g_tsub_sq[b*NSUB + m], coeff, g_lv[b*NSUB + m] * LOG2E_F);
        sB[m] = make_float4(s*bp[0], s*bp[1], s*bp[2], wv);
    }
    __syncthreads();
    int warp = tid >> 5, lane = tid & 31;
    int r0 = blockIdx.x * 32 + warp * 4;
    float ax[4], ay[4], az[4], C[4], px[4], py[4], pz[4];
#pragma unroll
    for (int q = 0; q < 4; q++) {
        const float* ap = &tmpl[(r0 + q)*3];
        ax[q] = ap[0]; ay[q] = ap[1]; az[q] = ap[2];
        C[q] = fmaf(g_tmpl_sq[r0 + q], coeff, g_lu[b*NSUB + r0 + q] * LOG2E_F);
        px[q] = 0.f; py[q] = 0.f; pz[q] = 0.f;
    }
    for (int m = lane; m < NSUB; m += 32) {
        float4 pb = sB[m];
#pragma unroll
        for (int q = 0; q < 4; q++) {
            float arg = fmaf(ax[q], pb.x, fmaf(ay[q], pb.y, fmaf(az[q], pb.z, pb.w)));
            float e = ex2(arg + C[q]);
            px[q] = fmaf(e, pb.x, px[q]);
            py[q] = fmaf(e, pb.y, py[q]);
            pz[q] = fmaf(e, pb.z, pz[q]);
        }
    }
#pragma unroll
    for (int q = 0; q < 4; q++) {
#pragma unroll
        for (int off = 16; off; off >>= 1) {
            px[q] += __shfl_xor_sync(0xffffffffu, px[q], off);
            py[q] += __shfl_xor_sync(0xffffffffu, py[q], off);
            pz[q] += __shfl_xor_sync(0xffffffffu, pz[q], off);
        }
    }
    if (lane == 0) {
#pragma unroll
        for (int q = 0; q < 4; q++) {
            float* o = &g_perm[(b*NSUB + r0 + q)*3];
            o[0] = px[q] * inv_s; o[1] = py[q] * inv_s; o[2] = pz[q] * inv_s;
        }
    }
}

__global__ void __launch_bounds__(256) k_enc(const float* __restrict__ W, const float* __restrict__ be) {
    __shared__ float sP[NSUB*3];
    int b = blockIdx.x, tid = threadIdx.x;
    for (int i = tid; i < NSUB*3; i += 256) sP[i] = g_tsub[b*NSUB*3 + i];
    __syncthreads();
    float wx = W[tid], wy = W[256 + tid], wz = W[512 + tid], bb = be[tid];
    float zm = 0.0f;
    for (int m = 0; m < NSUB; m++) {
        float v = fmaf(sP[m*3], wx, fmaf(sP[m*3+1], wy, fmaf(sP[m*3+2], wz, bb)));
        zm = fmaxf(zm, fmaxf(v, 0.0f));
    }
    g_z[b*DZ + tid] = zm;
}

__global__ void __launch_bounds__(256) k_bias(const float* __restrict__ W1, const float* __restrict__ b1,
                                              const float* __restrict__ t) {
    __shared__ float sZ[DZ];
    int b = blockIdx.x, c = threadIdx.x;
    sZ[c] = g_z[b*DZ + c];
    __syncthreads();
    float tc = fminf(fmaxf(t[b], 1e-5f), 1.0f - 1e-5f);
    float acc = fmaf(tc, W1[3*DH + c], b1[c]);
    for (int k = 0; k < DZ; k++)
        acc = fmaf(sZ[k], W1[(4 + k)*DH + c], acc);
    g_bb[b*DH + c] = acc;
}

__global__ void __launch_bounds__(256) k_mlp(const float* __restrict__ tmpl, const float* __restrict__ W1,
                                             const float* __restrict__ W2, const float* __restrict__ b2,
                                             const float* __restrict__ t) {
    __shared__ float sBB[DH], sWa[DH], sWb[DH], sWc[DH], sW2[DH*3];
    int b = blockIdx.y, tid = threadIdx.x;
    sBB[tid] = g_bb[b*DH + tid];
    sWa[tid] = W1[0*DH + tid];
    sWb[tid] = W1[1*DH + tid];
    sWc[tid] = W1[2*DH + tid];
    for (int i = tid; i < DH*3; i += 256) sW2[i] = W2[i];
    __syncthreads();
    int warp = tid >> 5, lane = tid & 31;
    float tc = fminf(fmaxf(t[b], 1e-5f), 1.0f - 1e-5f);
    float u = 1.0f - tc;
    float b20 = b2[0], b21 = b2[1], b22 = b2[2];
    double vacc = 0.0;
    for (int q = 0; q < 4; q++) {
        int p = blockIdx.x * 32 + warp * 4 + q;
        float tmx = tmpl[p*3], tmy = tmpl[p*3+1], tmz = tmpl[p*3+2];
        const float* pp = &g_perm[(b*NSUB + p)*3];
        float pmx = pp[0], pmy = pp[1], pmz = pp[2];
        float x0 = u*tmx + tc*pmx, x1 = u*tmy + tc*pmy, x2 = u*tmz + tc*pmz;
        float a0 = 0.f, a1 = 0.f, a2 = 0.f;
#pragma unroll
        for (int k = 0; k < 8; k++) {
            int c = lane + k*32;
            float h = fmaf(x0, sWa[c], fmaf(x1, sWb[c], fmaf(x2, sWc[c], sBB[c])));
            h = fmaxf(h, 0.0f);
            a0 = fmaf(h, sW2[c*3+0], a0);
            a1 = fmaf(h, sW2[c*3+1], a1);
            a2 = fmaf(h, sW2[c*3+2], a2);
        }
#pragma unroll
        for (int off = 16; off; off >>= 1) {
            a0 += __shfl_xor_sync(0xffffffffu, a0, off);
            a1 += __shfl_xor_sync(0xffffffffu, a1, off);
            a2 += __shfl_xor_sync(0xffffffffu, a2, off);
        }
        if (lane == 0) {
            float v0 = a0 + b20, v1 = a1 + b21, v2 = a2 + b22;
            float d0 = v0 - (pmx - tmx), d1 = v1 - (pmy - tmy), d2 = v2 - (pmz - tmz);
            vacc += (double)(d0*d0) + (double)(d1*d1) + (double)(d2*d2);
            float xx = tmx + v0, xy = tmy + v1, xz = tmz + v2;
            float* o = &g_x1[(b*NSUB + p)*3];
            o[0] = xx; o[1] = xy; o[2] = xz;
            g_x1_sq[b*NSUB + p] = xx*xx + xy*xy + xz*xz;
        }
    }
    if (lane == 0) atomicAdd(&g_vel_sum, vacc);
}

__global__ void __launch_bounds__(512) k_otacc() {
    __shared__ double sred[512];
    int tid = threadIdx.x;
    double acc = 0.0;
    for (int i = tid; i < BATCH*NSUB; i += 512) {
        acc += (double)g_f1[i] + (double)g_g1[i];
        acc -= 0.5 * ((double)g_f2[i] + (double)g_g2[i]);
        acc -= 0.5 * ((double)g_f3[i] + (double)g_g3[i]);
    }
    sred[tid] = acc;
    __syncthreads();
    for (int s = 256; s; s >>= 1) {
        if (tid < s) sred[tid] += sred[tid + s];
        __syncthreads();
    }
    if (tid == 0) g_ot_sum = sred[0] / (double)(NSUB * BATCH);
}

__global__ void k_final(float* __restrict__ out) {
    float lv  = (float)(g_vel_sum / (double)(BATCH * NSUB * 3));
    float lot = (float)g_ot_sum;
    float lrg = (float)(g_reg_sum / (double)NSUB);
    out[0] = lv + 0.1f * lot + 0.01f * lrg;
    out[1] = lv;
    out[2] = lot;
    out[3] = lrg;
}

extern "C" void kernel_launch(void* const* d_in, const int* in_sizes, int n_in,
                              void* d_out, int out_size) {
    const float* target = (const float*)d_in[0];
    const float* t      = (const float*)d_in[1];
    const float* tmpl   = (const float*)d_in[2];
    const float* W_enc  = (const float*)d_in[3];
    const float* b_enc  = (const float*)d_in[4];
    const float* W1     = (const float*)d_in[5];
    const float* b1     = (const float*)d_in[6];
    const float* W2     = (const float*)d_in[7];
    const float* b2     = (const float*)d_in[8];
    float* out = (float*)d_out;

    float *p_tsub, *p_tsq, *p_tmsq, *p_lu, *p_lv, *p_x1, *p_x1sq;
    float *p_f1, *p_g1, *p_f2, *p_g2, *p_f3, *p_g3;
    cudaGetSymbolAddress((void**)&p_tsub, g_tsub);
    cudaGetSymbolAddress((void**)&p_tsq,  g_tsub_sq);
    cudaGetSymbolAddress((void**)&p_tmsq, g_tmpl_sq);
    cudaGetSymbolAddress((void**)&p_lu,   g_lu);
    cudaGetSymbolAddress((void**)&p_lv,   g_lv);
    cudaGetSymbolAddress((void**)&p_x1,   g_x1);
    cudaGetSymbolAddress((void**)&p_x1sq, g_x1_sq);
    cudaGetSymbolAddress((void**)&p_f1,   g_f1);
    cudaGetSymbolAddress((void**)&p_g1,   g_g1);
    cudaGetSymbolAddress((void**)&p_f2,   g_f2);
    cudaGetSymbolAddress((void**)&p_g2,   g_g2);
    cudaGetSymbolAddress((void**)&p_f3,   g_f3);
    cudaGetSymbolAddress((void**)&p_g3,   g_g3);

    const int SPB = NSUB*3, QB = NSUB;
    const float LOGN = -logf((float)NSUB);
    const float EPS = 0.0025f;
    const float CA  = -20.0f  * LOG2E_F;
    const float CO  = -200.0f * LOG2E_F;
    const float WM_A = LOG2E_F;
    const float WM_O = 400.0f * LOG2E_F;
    const float WA_O = LOGN * LOG2E_F;
    dim3 gL2(NSUB/32, BATCH, 2);

    k_init<<<1,1>>>();
    k_tmpl<<<NSUB/256,256>>>(tmpl);
    k_zero_all<<<(BATCH*NSUB)/256,256>>>();
    k_fps<<<BATCH*FPSC, 1024>>>(target);

    // Phase A: Sinkhorn assignment (z=0) fused with self-OT on tsub (z=1)
    for (int it = 0; it < 20; it++) {
        RunDesc a0 = { tmpl, p_tmsq, p_tsub, p_tsq, p_lv, p_lu,
                       0, 0, SPB, QB, WM_A, 0.0f, CA, -1.0f };
        RunDesc a1 = { p_tsub, p_tsq, p_tsub, p_tsq, p_g3, p_f3,
                       SPB, QB, SPB, QB, WM_O, WA_O, CO, -EPS };
        k_lse2<<<gL2,256>>>(a0, a1);
        RunDesc b0 = { p_tsub, p_tsq, tmpl, p_tmsq, p_lu, p_lv,
                       SPB, QB, 0, 0, WM_A, 0.0f, CA, -1.0f };
        RunDesc b1 = { p_tsub, p_tsq, p_tsub, p_tsq, p_f3, p_g3,
                       SPB, QB, SPB, QB, WM_O, WA_O, CO, -EPS };
        k_lse2<<<gL2,256>>>(b0, b1);
    }
    {
        dim3 gP(NSUB/32, BATCH);
        k_perm<<<gP,256>>>(tmpl);
        k_enc<<<BATCH,256>>>(W_enc, b_enc);
        k_bias<<<BATCH,256>>>(W1, b1, t);
        k_mlp<<<gP,256>>>(tmpl, W1, W2, b2, t);
    }
    // Phase B: OT(x1,tsub) (z=0) fused with self-OT(x1,x1) (z=1)
    for (int it = 0; it < 20; it++) {
        RunDesc a0 = { p_x1, p_x1sq, p_tsub, p_tsq, p_g1, p_f1,
                       SPB, QB, SPB, QB, WM_O, WA_O, CO, -EPS };
        RunDesc a1 = { p_x1, p_x1sq, p_x1, p_x1sq, p_g2, p_f2,
                       SPB, QB, SPB, QB, WM_O, WA_O, CO, -EPS };
        k_lse2<<<gL2,256>>>(a0, a1);
        RunDesc b0 = { p_tsub, p_tsq, p_x1, p_x1sq, p_f1, p_g1,
                       SPB, QB, SPB, QB, WM_O, WA_O, CO, -EPS };
        RunDesc b1 = { p_x1, p_x1sq, p_x1, p_x1sq, p_f2, p_g2,
                       SPB, QB, SPB, QB, WM_O, WA_O, CO, -EPS };
        k_lse2<<<gL2,256>>>(b0, b1);
    }
    k_otacc<<<1,512>>>();
    k_final<<<1,1>>>(out);
}

// round 17
// speedup vs baseline: 1.1389x; 1.0222x over previous
#include <cuda_runtime.h>
#include <math_constants.h>
#include <math.h>
#include <cstdint>

#define BATCH 8
#define NPTS 16384
#define NSUB 2048
#define DZ 256
#define DH 256
#define FPSC 8
#define PPC (NPTS/FPSC)
#define PPT (PPC/1024)

#define LOG2E_F 1.4426950408889634f
#define LN2_F   0.6931471805599453f

__device__ __forceinline__ float ex2(float x) {
    float y;
    asm("ex2.approx.ftz.f32 %0, %1;" : "=f"(y) : "f"(x));
    return y;
}

// ---- scratch (device globals; allocation is forbidden) ----
__device__ float g_tsub[BATCH*NSUB*3];
__device__ float g_tsub_sq[BATCH*NSUB];
__device__ float g_tmpl_sq[NSUB];
__device__ float g_lu[BATCH*NSUB];
__device__ float g_lv[BATCH*NSUB];
__device__ float g_perm[BATCH*NSUB*3];
__device__ float g_z[BATCH*DZ];
__device__ float g_bb[BATCH*DH];
__device__ float g_x1[BATCH*NSUB*3];
__device__ float g_x1_sq[BATCH*NSUB];
__device__ float g_f1[BATCH*NSUB];
__device__ float g_g1[BATCH*NSUB];
__device__ float g_f2[BATCH*NSUB];
__device__ float g_g2[BATCH*NSUB];
__device__ float g_f3[BATCH*NSUB];
__device__ float g_g3[BATCH*NSUB];
__device__ double g_vel_sum;
__device__ double g_ot_sum;
__device__ double g_reg_sum;

__global__ void k_init() { g_vel_sum = 0.0; g_ot_sum = 0.0; g_reg_sum = 0.0; }

__global__ void k_zero_all() {
    int i = blockIdx.x * blockDim.x + threadIdx.x;
    if (i < BATCH*NSUB) {
        g_lu[i] = 0.f; g_lv[i] = 0.f;
        g_f1[i] = 0.f; g_g1[i] = 0.f;
        g_f2[i] = 0.f; g_g2[i] = 0.f;
        g_f3[i] = 0.f; g_g3[i] = 0.f;
    }
}

__global__ void k_tmpl(const float* __restrict__ tmpl) {
    __shared__ double sred[256];
    int n = blockIdx.x * 256 + threadIdx.x;
    float tx = tmpl[n*3+0], ty = tmpl[n*3+1], tz = tmpl[n*3+2];
    float sq = tx*tx + ty*ty + tz*tz;
    g_tmpl_sq[n] = sq;
    float d = sqrtf(sq) - 1.0f;
    sred[threadIdx.x] = (double)(d * d);
    __syncthreads();
    for (int s = 128; s; s >>= 1) {
        if (threadIdx.x < s) sred[threadIdx.x] += sred[threadIdx.x + s];
        __syncthreads();
    }
    if (threadIdx.x == 0) atomicAdd(&g_reg_sum, sred[0]);
}

// ---------------- FPS: 8-CTA cluster, DSMEM mbarrier handshake ----------------
__device__ __forceinline__ void st_cluster_f4(unsigned int saddr, unsigned int rank, float4 v) {
    unsigned int ra;
    asm volatile("mapa.shared::cluster.u32 %0, %1, %2;" : "=r"(ra) : "r"(saddr), "r"(rank));
    asm volatile("st.shared::cluster.v4.f32 [%0], {%1,%2,%3,%4};"
                 :: "r"(ra), "f"(v.x), "f"(v.y), "f"(v.z), "f"(v.w) : "memory");
}
__device__ __forceinline__ void st_cluster_i32(unsigned int saddr, unsigned int rank, int v) {
    unsigned int ra;
    asm volatile("mapa.shared::cluster.u32 %0, %1, %2;" : "=r"(ra) : "r"(saddr), "r"(rank));
    asm volatile("st.shared::cluster.b32 [%0], %1;" :: "r"(ra), "r"(v) : "memory");
}
__device__ __forceinline__ void mbar_init(unsigned int saddr, unsigned int cnt) {
    asm volatile("mbarrier.init.shared.b64 [%0], %1;" :: "r"(saddr), "r"(cnt) : "memory");
}
__device__ __forceinline__ void mbar_arrive_peer(unsigned int saddr, unsigned int rank) {
    unsigned int ra;
    asm volatile("mapa.shared::cluster.u32 %0, %1, %2;" : "=r"(ra) : "r"(saddr), "r"(rank));
    asm volatile("mbarrier.arrive.release.cluster.shared::cluster.b64 _, [%0];"
                 :: "r"(ra) : "memory");
}
#define MBAR_WAIT_CL(mbar, par) do { \
    asm volatile( \
        "{\n\t.reg .pred P1;\n\t" \
        "W%=:\n\t" \
        "mbarrier.try_wait.parity.acquire.cluster.shared::cta.b64 P1, [%0], %1;\n\t" \
        "@!P1 bra W%=;\n\t" \
        "}" :: "r"(mbar), "r"(par) : "memory"); \
} while (0)
#define CLUSTER_SYNC_() do { \
    asm volatile("barrier.cluster.arrive.aligned;" ::: "memory"); \
    asm volatile("barrier.cluster.wait.aligned;" ::: "memory"); } while (0)

__global__ void __launch_bounds__(1024) __cluster_dims__(FPSC, 1, 1)
k_fps(const float* __restrict__ target) {
    __shared__ float ys[PPC], zs[PPC];
    __shared__ float rv[32]; __shared__ int ri[32];
    __shared__ float4 s_mb[2][FPSC]; __shared__ int s_mbi[2][FPSC];
    __shared__ float4 s_cand; __shared__ float s_bv; __shared__ int s_bi;
    __shared__ unsigned long long s_bar[2];
    int tid = threadIdx.x;
    unsigned int rank;
    asm("mov.u32 %0, %%cluster_ctarank;" : "=r"(rank));
    int b = blockIdx.x / FPSC;
    int base = (int)rank * PPC;
    const float* tg = target + (size_t)b * NPTS * 3 + (size_t)base * 3;
    unsigned int bar0 = (unsigned int)__cvta_generic_to_shared(&s_bar[0]);
    unsigned int bar1 = (unsigned int)__cvta_generic_to_shared(&s_bar[1]);
    unsigned int mb0f = (unsigned int)__cvta_generic_to_shared(&s_mb[0][rank]);
    unsigned int mb0i = (unsigned int)__cvta_generic_to_shared(&s_mbi[0][rank]);
    unsigned int mb1f = (unsigned int)__cvta_generic_to_shared(&s_mb[1][rank]);
    unsigned int mb1i = (unsigned int)__cvta_generic_to_shared(&s_mbi[1][rank]);
    float rx[PPT], dist[PPT];
#pragma unroll
    for (int j = 0; j < PPT; j++) {
        int n = tid + j * 1024;
        rx[j] = tg[n*3+0];
        ys[n] = tg[n*3+1];
        zs[n] = tg[n*3+2];
        dist[j] = CUDART_INF_F;
    }
    if (tid == 0) {
        mbar_init(bar0, FPSC);
        mbar_init(bar1, FPSC);
        s_cand = (rank == 0) ? make_float4(rx[0], ys[0], zs[0], 1.0f)
                             : make_float4(0.f, 0.f, 0.f, -1.0f);
        s_bi = base;
    }
    __syncthreads();
    CLUSTER_SYNC_();   // mbarrier init visible cluster-wide before any arrivals
    // bootstrap: each CTA delivers its proposal + one arrival to every peer's bar0
    if (tid < FPSC) {
        st_cluster_f4(mb0f, (unsigned int)tid, s_cand);
        st_cluster_i32(mb0i, (unsigned int)tid, s_bi);
        mbar_arrive_peer(bar0, (unsigned int)tid);
    }
    int ph0 = 0, ph1 = 0;
    for (int i = 0; i < NSUB; i++) {
        int par = i & 1;
        if (par == 0) { MBAR_WAIT_CL(bar0, ph0); if (tid == 0) {} ph0 ^= 1; }
        else          { MBAR_WAIT_CL(bar1, ph1); ph1 ^= 1; }
        // reduce 8 mailbox candidates (uniform across threads)
        float bvw = -CUDART_INF_F; int biw = 0x7fffffff;
        float cx = 0.f, cy = 0.f, cz = 0.f;
#pragma unroll
        for (int r = 0; r < FPSC; r++) {
            float4 c = s_mb[par][r]; int ci = s_mbi[par][r];
            if (c.w > bvw || (c.w == bvw && ci < biw)) {
                bvw = c.w; biw = ci; cx = c.x; cy = c.y; cz = c.z;
            }
        }
        if (rank == 0 && tid == 0) {
            float* o = &g_tsub[(b*NSUB + i)*3];
            o[0] = cx; o[1] = cy; o[2] = cz;
            g_tsub_sq[b*NSUB + i] = cx*cx + cy*cy + cz*cz;
        }
        // sweep (exact jnp arithmetic) + local argmax
        float bv = -1.0f; int bi = base;
#pragma unroll
        for (int j = 0; j < PPT; j++) {
            int n = tid + j * 1024;
            float dx = __fadd_rn(rx[j], -cx);
            float dy = __fadd_rn(ys[n], -cy);
            float dz = __fadd_rn(zs[n], -cz);
            float d  = __fadd_rn(__fadd_rn(__fmul_rn(dx,dx), __fmul_rn(dy,dy)), __fmul_rn(dz,dz));
            float nd = fminf(dist[j], d);
            dist[j] = nd;
            if (nd > bv) { bv = nd; bi = base + n; }
        }
#pragma unroll
        for (int off = 16; off; off >>= 1) {
            float ov = __shfl_xor_sync(0xffffffffu, bv, off);
            int   oi = __shfl_xor_sync(0xffffffffu, bi, off);
            if (ov > bv || (ov == bv && oi < bi)) { bv = ov; bi = oi; }
        }
        if ((tid & 31) == 0) { rv[tid >> 5] = bv; ri[tid >> 5] = bi; }
        __syncthreads();
        if (tid < 32) {
            bv = rv[tid]; bi = ri[tid];
#pragma unroll
            for (int off = 16; off; off >>= 1) {
                float ov = __shfl_xor_sync(0xffffffffu, bv, off);
                int   oi = __shfl_xor_sync(0xffffffffu, bi, off);
                if (ov > bv || (ov == bv && oi < bi)) { bv = ov; bi = oi; }
            }
            if (tid == 0) { s_bv = bv; s_bi = bi; }
        }
        __syncthreads();
        int wbi = s_bi;
        int loc = wbi - base;
        if ((loc & 1023) == tid) {
            int j = loc >> 10;
            float x = (j == 0) ? rx[0] : rx[PPT-1];
            s_cand = make_float4(x, ys[loc], zs[loc], s_bv);
        }
        __syncthreads();   // all threads past reads of buffer par & s_cand ready
        if (tid < FPSC) {
            if (par == 0) {
                st_cluster_f4(mb1f, (unsigned int)tid, s_cand);
                st_cluster_i32(mb1i, (unsigned int)tid, wbi);
                mbar_arrive_peer(bar1, (unsigned int)tid);
            } else {
                st_cluster_f4(mb0f, (unsigned int)tid, s_cand);
                st_cluster_i32(mb0i, (unsigned int)tid, wbi);
                mbar_arrive_peer(bar0, (unsigned int)tid);
            }
        }
    }
    CLUSTER_SYNC_();   // keep SMEM resident for in-flight peer stores
}

struct RunDesc {
    const float *aPts, *aSq, *bPts, *bSq, *w;
    float *out;
    int aPB, aSB, bPB, bSB;
    float wMul, wAdd, coeff, outScale;  // log2-domain
};

// out[b][r] = outScale * ln-LSE_m(...); log2-domain args; CHUNKED max (R16, known good)
__global__ void __launch_bounds__(256) k_lse2(RunDesc d0, RunDesc d1) {
    __shared__ float4 sB[NSUB];
    RunDesc d = (blockIdx.z == 0) ? d0 : d1;
    int b = blockIdx.y, tid = threadIdx.x;
    float coeff = d.coeff;
    float s = -2.0f * coeff;
    for (int m = tid; m < NSUB; m += 256) {
        const float* bp = d.bPts + b*d.bPB + m*3;
        float wv = fmaf(d.w[b*NSUB + m], d.wMul, d.wAdd);
        wv = fmaf(d.bSq[b*d.bSB + m], coeff, wv);
        sB[m] = make_float4(s*bp[0], s*bp[1], s*bp[2], wv);
    }
    __syncthreads();
    int warp = tid >> 5, lane = tid & 31;
    int r0 = blockIdx.x * 32 + warp * 4;
    float ax[4], ay[4], az[4], A[4], mr[4], sr[4];
#pragma unroll
    for (int q = 0; q < 4; q++) {
        const float* ap = d.aPts + b*d.aPB + (r0 + q)*3;
        ax[q] = ap[0]; ay[q] = ap[1]; az[q] = ap[2];
        A[q] = coeff * d.aSq[b*d.aSB + r0 + q];
        mr[q] = -CUDART_INF_F; sr[q] = 0.f;
    }
#pragma unroll 2
    for (int m0 = lane; m0 < NSUB; m0 += 128) {
        float4 p0 = sB[m0];
        float4 p1 = sB[m0 + 32];
        float4 p2 = sB[m0 + 64];
        float4 p3 = sB[m0 + 96];
#pragma unroll
        for (int q = 0; q < 4; q++) {
            float a0 = fmaf(ax[q], p0.x, fmaf(ay[q], p0.y, fmaf(az[q], p0.z, p0.w)));
            float a1 = fmaf(ax[q], p1.x, fmaf(ay[q], p1.y, fmaf(az[q], p1.z, p1.w)));
            float a2 = fmaf(ax[q], p2.x, fmaf(ay[q], p2.y, fmaf(az[q], p2.z, p2.w)));
            float a3 = fmaf(ax[q], p3.x, fmaf(ay[q], p3.y, fmaf(az[q], p3.z, p3.w)));
            float cm = fmaxf(fmaxf(a0, a1), fmaxf(a2, a3));
            float nm = fmaxf(mr[q], cm);
            float cs = (ex2(a0 - nm) + ex2(a1 - nm)) + (ex2(a2 - nm) + ex2(a3 - nm));
            sr[q] = fmaf(sr[q], ex2(mr[q] - nm), cs);
            mr[q] = nm;
        }
    }
#pragma unroll
    for (int q = 0; q < 4; q++) {
#pragma unroll
        for (int off = 16; off; off >>= 1) {
            float om = __shfl_xor_sync(0xffffffffu, mr[q], off);
            float os = __shfl_xor_sync(0xffffffffu, sr[q], off);
            float nm = fmaxf(mr[q], om);
            sr[q] = fmaf(sr[q], ex2(mr[q]-nm), os * ex2(om-nm));
            mr[q] = nm;
        }
    }
    if (lane == 0) {
#pragma unroll
        for (int q = 0; q < 4; q++) {
            float lse = fmaf(mr[q] + A[q], LN2_F, logf(sr[q]));
            d.out[b*NSUB + r0 + q] = d.outScale * lse;
        }
    }
}

// target_perm = P @ target_sub; log2-domain args.
__global__ void __launch_bounds__(256) k_perm(const float* __restrict__ tmpl) {
    __shared__ float4 sB[NSUB];
    int b = blockIdx.y, tid = threadIdx.x;
    const float coeff = -20.0f * LOG2E_F;
    const float s = 40.0f * LOG2E_F;
    const float inv_s = 1.0f / (40.0f * LOG2E_F);
    for (int m = tid; m < NSUB; m += 256) {
        const float* bp = &g_tsub[(b*NSUB + m)*3];
        float wv = fmaf(g_tsub_sq[b*NSUB + m], coeff, g_lv[b*NSUB + m] * LOG2E_F);
        sB[m] = make_float4(s*bp[0], s*bp[1], s*bp[2], wv);
    }
    __syncthreads();
    int warp = tid >> 5, lane = tid & 31;
    int r0 = blockIdx.x * 32 + warp * 4;
    float ax[4], ay[4], az[4], C[4], px[4], py[4], pz[4];
#pragma unroll
    for (int q = 0; q < 4; q++) {
        const float* ap = &tmpl[(r0 + q)*3];
        ax[q] = ap[0]; ay[q] = ap[1]; az[q] = ap[2];
        C[q] = fmaf(g_tmpl_sq[r0 + q], coeff, g_lu[b*NSUB + r0 + q] * LOG2E_F);
        px[q] = 0.f; py[q] = 0.f; pz[q] = 0.f;
    }
    for (int m = lane; m < NSUB; m += 32) {
        float4 pb = sB[m];
#pragma unroll
        for (int q = 0; q < 4; q++) {
            float arg = fmaf(ax[q], pb.x, fmaf(ay[q], pb.y, fmaf(az[q], pb.z, pb.w)));
            float e = ex2(arg + C[q]);
            px[q] = fmaf(e, pb.x, px[q]);
            py[q] = fmaf(e, pb.y, py[q]);
            pz[q] = fmaf(e, pb.z, pz[q]);
        }
    }
#pragma unroll
    for (int q = 0; q < 4; q++) {
#pragma unroll
        for (int off = 16; off; off >>= 1) {
            px[q] += __shfl_xor_sync(0xffffffffu, px[q], off);
            py[q] += __shfl_xor_sync(0xffffffffu, py[q], off);
            pz[q] += __shfl_xor_sync(0xffffffffu, pz[q], off);
        }
    }
    if (lane == 0) {
#pragma unroll
        for (int q = 0; q < 4; q++) {
            float* o = &g_perm[(b*NSUB + r0 + q)*3];
            o[0] = px[q] * inv_s; o[1] = py[q] * inv_s; o[2] = pz[q] * inv_s;
        }
    }
}

__global__ void __launch_bounds__(256) k_enc(const float* __restrict__ W, const float* __restrict__ be) {
    __shared__ float sP[NSUB*3];
    int b = blockIdx.x, tid = threadIdx.x;
    for (int i = tid; i < NSUB*3; i += 256) sP[i] = g_tsub[b*NSUB*3 + i];
    __syncthreads();
    float wx = W[tid], wy = W[256 + tid], wz = W[512 + tid], bb = be[tid];
    float zm = 0.0f;
    for (int m = 0; m < NSUB; m++) {
        float v = fmaf(sP[m*3], wx, fmaf(sP[m*3+1], wy, fmaf(sP[m*3+2], wz, bb)));
        zm = fmaxf(zm, fmaxf(v, 0.0f));
    }
    g_z[b*DZ + tid] = zm;
}

__global__ void __launch_bounds__(256) k_bias(const float* __restrict__ W1, const float* __restrict__ b1,
                                              const float* __restrict__ t) {
    __shared__ float sZ[DZ];
    int b = blockIdx.x, c = threadIdx.x;
    sZ[c] = g_z[b*DZ + c];
    __syncthreads();
    float tc = fminf(fmaxf(t[b], 1e-5f), 1.0f - 1e-5f);
    float acc = fmaf(tc, W1[3*DH + c], b1[c]);
    for (int k = 0; k < DZ; k++)
        acc = fmaf(sZ[k], W1[(4 + k)*DH + c], acc);
    g_bb[b*DH + c] = acc;
}

__global__ void __launch_bounds__(256) k_mlp(const float* __restrict__ tmpl, const float* __restrict__ W1,
                                             const float* __restrict__ W2, const float* __restrict__ b2,
                                             const float* __restrict__ t) {
    __shared__ float sBB[DH], sWa[DH], sWb[DH], sWc[DH], sW2[DH*3];
    int b = blockIdx.y, tid = threadIdx.x;
    sBB[tid] = g_bb[b*DH + tid];
    sWa[tid] = W1[0*DH + tid];
    sWb[tid] = W1[1*DH + tid];
    sWc[tid] = W1[2*DH + tid];
    for (int i = tid; i < DH*3; i += 256) sW2[i] = W2[i];
    __syncthreads();
    int warp = tid >> 5, lane = tid & 31;
    float tc = fminf(fmaxf(t[b], 1e-5f), 1.0f - 1e-5f);
    float u = 1.0f - tc;
    float b20 = b2[0], b21 = b2[1], b22 = b2[2];
    double vacc = 0.0;
    for (int q = 0; q < 4; q++) {
        int p = blockIdx.x * 32 + warp * 4 + q;
        float tmx = tmpl[p*3], tmy = tmpl[p*3+1], tmz = tmpl[p*3+2];
        const float* pp = &g_perm[(b*NSUB + p)*3];
        float pmx = pp[0], pmy = pp[1], pmz = pp[2];
        float x0 = u*tmx + tc*pmx, x1 = u*tmy + tc*pmy, x2 = u*tmz + tc*pmz;
        float a0 = 0.f, a1 = 0.f, a2 = 0.f;
#pragma unroll
        for (int k = 0; k < 8; k++) {
            int c = lane + k*32;
            float h = fmaf(x0, sWa[c], fmaf(x1, sWb[c], fmaf(x2, sWc[c], sBB[c])));
            h = fmaxf(h, 0.0f);
            a0 = fmaf(h, sW2[c*3+0], a0);
            a1 = fmaf(h, sW2[c*3+1], a1);
            a2 = fmaf(h, sW2[c*3+2], a2);
        }
#pragma unroll
        for (int off = 16; off; off >>= 1) {
            a0 += __shfl_xor_sync(0xffffffffu, a0, off);
            a1 += __shfl_xor_sync(0xffffffffu, a1, off);
            a2 += __shfl_xor_sync(0xffffffffu, a2, off);
        }
        if (lane == 0) {
            float v0 = a0 + b20, v1 = a1 + b21, v2 = a2 + b22;
            float d0 = v0 - (pmx - tmx), d1 = v1 - (pmy - tmy), d2 = v2 - (pmz - tmz);
            vacc += (double)(d0*d0) + (double)(d1*d1) + (double)(d2*d2);
            float xx = tmx + v0, xy = tmy + v1, xz = tmz + v2;
            float* o = &g_x1[(b*NSUB + p)*3];
            o[0] = xx; o[1] = xy; o[2] = xz;
            g_x1_sq[b*NSUB + p] = xx*xx + xy*xy + xz*xz;
        }
    }
    if (lane == 0) atomicAdd(&g_vel_sum, vacc);
}

__global__ void __launch_bounds__(512) k_otacc() {
    __shared__ double sred[512];
    int tid = threadIdx.x;
    double acc = 0.0;
    for (int i = tid; i < BATCH*NSUB; i += 512) {
        acc += (double)g_f1[i] + (double)g_g1[i];
        acc -= 0.5 * ((double)g_f2[i] + (double)g_g2[i]);
        acc -= 0.5 * ((double)g_f3[i] + (double)g_g3[i]);
    }
    sred[tid] = acc;
    __syncthreads();
    for (int s = 256; s; s >>= 1) {
        if (tid < s) sred[tid] += sred[tid + s];
        __syncthreads();
    }
    if (tid == 0) g_ot_sum = sred[0] / (double)(NSUB * BATCH);
}

__global__ void k_final(float* __restrict__ out) {
    float lv  = (float)(g_vel_sum / (double)(BATCH * NSUB * 3));
    float lot = (float)g_ot_sum;
    float lrg = (float)(g_reg_sum / (double)NSUB);
    out[0] = lv + 0.1f * lot + 0.01f * lrg;
    out[1] = lv;
    out[2] = lot;
    out[3] = lrg;
}

extern "C" void kernel_launch(void* const* d_in, const int* in_sizes, int n_in,
                              void* d_out, int out_size) {
    const float* target = (const float*)d_in[0];
    const float* t      = (const float*)d_in[1];
    const float* tmpl   = (const float*)d_in[2];
    const float* W_enc  = (const float*)d_in[3];
    const float* b_enc  = (const float*)d_in[4];
    const float* W1     = (const float*)d_in[5];
    const float* b1     = (const float*)d_in[6];
    const float* W2     = (const float*)d_in[7];
    const float* b2     = (const float*)d_in[8];
    float* out = (float*)d_out;

    float *p_tsub, *p_tsq, *p_tmsq, *p_lu, *p_lv, *p_x1, *p_x1sq;
    float *p_f1, *p_g1, *p_f2, *p_g2, *p_f3, *p_g3;
    cudaGetSymbolAddress((void**)&p_tsub, g_tsub);
    cudaGetSymbolAddress((void**)&p_tsq,  g_tsub_sq);
    cudaGetSymbolAddress((void**)&p_tmsq, g_tmpl_sq);
    cudaGetSymbolAddress((void**)&p_lu,   g_lu);
    cudaGetSymbolAddress((void**)&p_lv,   g_lv);
    cudaGetSymbolAddress((void**)&p_x1,   g_x1);
    cudaGetSymbolAddress((void**)&p_x1sq, g_x1_sq);
    cudaGetSymbolAddress((void**)&p_f1,   g_f1);
    cudaGetSymbolAddress((void**)&p_g1,   g_g1);
    cudaGetSymbolAddress((void**)&p_f2,   g_f2);
    cudaGetSymbolAddress((void**)&p_g2,   g_g2);
    cudaGetSymbolAddress((void**)&p_f3,   g_f3);
    cudaGetSymbolAddress((void**)&p_g3,   g_g3);

    const int SPB = NSUB*3, QB = NSUB;
    const float LOGN = -logf((float)NSUB);
    const float EPS = 0.0025f;
    const float CA  = -20.0f  * LOG2E_F;
    const float CO  = -200.0f * LOG2E_F;
    const float WM_A = LOG2E_F;
    const float WM_O = 400.0f * LOG2E_F;
    const float WA_O = LOGN * LOG2E_F;
    dim3 gL2(NSUB/32, BATCH, 2);

    k_init<<<1,1>>>();
    k_tmpl<<<NSUB/256,256>>>(tmpl);
    k_zero_all<<<(BATCH*NSUB)/256,256>>>();
    k_fps<<<BATCH*FPSC, 1024>>>(target);

    // Phase A: Sinkhorn assignment (z=0) fused with self-OT on tsub (z=1)
    for (int it = 0; it < 20; it++) {
        RunDesc a0 = { tmpl, p_tmsq, p_tsub, p_tsq, p_lv, p_lu,
                       0, 0, SPB, QB, WM_A, 0.0f, CA, -1.0f };
        RunDesc a1 = { p_tsub, p_tsq, p_tsub, p_tsq, p_g3, p_f3,
                       SPB, QB, SPB, QB, WM_O, WA_O, CO, -EPS };
        k_lse2<<<gL2,256>>>(a0, a1);
        RunDesc b0 = { p_tsub, p_tsq, tmpl, p_tmsq, p_lu, p_lv,
                       SPB, QB, 0, 0, WM_A, 0.0f, CA, -1.0f };
        RunDesc b1 = { p_tsub, p_tsq, p_tsub, p_tsq, p_f3, p_g3,
                       SPB, QB, SPB, QB, WM_O, WA_O, CO, -EPS };
        k_lse2<<<gL2,256>>>(b0, b1);
    }
    {
        dim3 gP(NSUB/32, BATCH);
        k_perm<<<gP,256>>>(tmpl);
        k_enc<<<BATCH,256>>>(W_enc, b_enc);
        k_bias<<<BATCH,256>>>(W1, b1, t);
        k_mlp<<<gP,256>>>(tmpl, W1, W2, b2, t);
    }
    // Phase B: OT(x1,tsub) (z=0) fused with self-OT(x1,x1) (z=1)
    for (int it = 0; it < 20; it++) {
        RunDesc a0 = { p_x1, p_x1sq, p_tsub, p_tsq, p_g1, p_f1,
                       SPB, QB, SPB, QB, WM_O, WA_O, CO, -EPS };
        RunDesc a1 = { p_x1, p_x1sq, p_x1, p_x1sq, p_g2, p_f2,
                       SPB, QB, SPB, QB, WM_O, WA_O, CO, -EPS };
        k_lse2<<<gL2,256>>>(a0, a1);
        RunDesc b0 = { p_tsub, p_tsq, p_x1, p_x1sq, p_f1, p_g1,
                       SPB, QB, SPB, QB, WM_O, WA_O, CO, -EPS };
        RunDesc b1 = { p_x1, p_x1sq, p_x1, p_x1sq, p_f2, p_g2,
                       SPB, QB, SPB, QB, WM_O, WA_O, CO, -EPS };
        k_lse2<<<gL2,256>>>(b0, b1);
    }
    k_otacc<<<1,512>>>();
    k_final<<<1,1>>>(out);
}